// round 12
// baseline (speedup 1.0000x reference)
#include <cuda_runtime.h>
#include <cuda_bf16.h>
#include <math.h>
#include <stdint.h>

#define T_TOK 256
#define H_DIM 1024
#define I_DIM 512
#define E_EXP 32
#define TOPK  8
#define NGRP  8
#define GSZ   4
#define TKG   4

#define SWZB(o) ((o) ^ (((o) >> 3) & 0x70))

// ---------------- helpers ----------------
__device__ __forceinline__ uint32_t smem_u32(const void* p) {
    uint32_t a;
    asm("{ .reg .u64 t; cvta.to.shared.u64 t, %1; cvt.u32.u64 %0, t; }" : "=r"(a) : "l"(p));
    return a;
}

// split 2 fp32 -> packed bf16x2 hi + bf16x2 lo (lo = exact residual)
__device__ __forceinline__ void bsplit2(float e0, float e1, uint32_t &h, uint32_t &l) {
    asm("cvt.rn.bf16x2.f32 %0, %1, %2;" : "=r"(h) : "f"(e1), "f"(e0));
    float f0 = __uint_as_float(h << 16);
    float f1 = __uint_as_float(h & 0xFFFF0000u);
    float r0 = e0 - f0, r1 = e1 - f1;
    asm("cvt.rn.bf16x2.f32 %0, %1, %2;" : "=r"(l) : "f"(r1), "f"(r0));
}

__device__ __forceinline__ void ldm4(uint32_t r[4], uint32_t addr) {
    asm volatile("ldmatrix.sync.aligned.m8n8.x4.shared.b16 {%0,%1,%2,%3}, [%4];"
        : "=r"(r[0]), "=r"(r[1]), "=r"(r[2]), "=r"(r[3]) : "r"(addr));
}

__device__ __forceinline__ void mma16816(float d[4], const uint32_t a[4],
                                         uint32_t b0, uint32_t b1) {
    asm volatile("mma.sync.aligned.m16n8k16.row.col.f32.bf16.bf16.f32 "
        "{%0,%1,%2,%3}, {%4,%5,%6,%7}, {%8,%9}, {%0,%1,%2,%3};"
        : "+f"(d[0]), "+f"(d[1]), "+f"(d[2]), "+f"(d[3])
        : "r"(a[0]), "r"(a[1]), "r"(a[2]), "r"(a[3]), "r"(b0), "r"(b1));
}

__device__ __forceinline__ void cpa16(uint32_t dst, const void* src, uint32_t sz) {
    asm volatile("cp.async.cg.shared.global [%0], [%1], 16, %2;"
        :: "r"(dst), "l"(src), "r"(sz) : "memory");
}
#define CPA_COMMIT() asm volatile("cp.async.commit_group;" ::: "memory")
#define CPA_WAIT0()  asm volatile("cp.async.wait_group 0;" ::: "memory")

// ---------------- device scratch ----------------
__device__ int   g_topk_idx[T_TOK * TOPK];
__device__ float g_topk_w[T_TOK * TOPK];
__device__ int   g_cnt[E_EXP];
__device__ int   g_tok[E_EXP * T_TOK];
__device__ int   g_slot[E_EXP * T_TOK];
__device__ float g_wt[E_EXP * T_TOK];
__device__ uint16_t g_xhi[T_TOK * H_DIM];
__device__ uint16_t g_xlo[T_TOK * H_DIM];
__device__ uint16_t g_ahi[T_TOK * TOPK * I_DIM];
__device__ uint16_t g_alo[T_TOK * TOPK * I_DIM];
__device__ float g_ybuf[T_TOK * TOPK * H_DIM];

// work queue
__device__ int g_pairs[E_EXP * 4];   // (e<<2)|mt
__device__ int g_npair;
__device__ int g_ctr;
__device__ int g_rdy[E_EXP * 4];     // per-pair gateup completion count (target 8)

// ---------------- kernel 1: routing (coalesced GEMV + fused x split) ----------------
__global__ __launch_bounds__(128) void routing_kernel(
    const float* __restrict__ x, const float* __restrict__ gate_w,
    const float* __restrict__ bias)
{
    int t = blockIdx.x;
    __shared__ float xs[H_DIM];
    __shared__ float part[4][E_EXP];
    __shared__ float sc[E_EXP];
    __shared__ float sfc[E_EXP];
    int tid = threadIdx.x;
    for (int i = tid; i < H_DIM / 4; i += 128) {
        float4 v = *(const float4*)(x + (size_t)t * H_DIM + i * 4);
        *(float4*)&xs[i * 4] = v;
        uint32_t h0, l0, h1, l1;
        bsplit2(v.x, v.y, h0, l0);
        bsplit2(v.z, v.w, h1, l1);
        ((uint2*)(g_xhi + (size_t)t * H_DIM))[i] = make_uint2(h0, h1);
        ((uint2*)(g_xlo + (size_t)t * H_DIM))[i] = make_uint2(l0, l1);
    }
    __syncthreads();
    int warp = tid >> 5, lane = tid & 31;
    {
        float s = 0.f;
        const float* gw = gate_w + lane;
        int h0 = warp * (H_DIM / 4);
        #pragma unroll 4
        for (int h = h0; h < h0 + H_DIM / 4; h++)
            s += xs[h] * gw[(size_t)h * E_EXP];
        part[warp][lane] = s;
    }
    __syncthreads();
    if (tid < E_EXP) {
        float s = part[0][tid] + part[1][tid] + part[2][tid] + part[3][tid];
        float sig = 1.f / (1.f + expf(-s));
        sc[tid] = sig;
        sfc[tid] = sig + bias[tid];
    }
    __syncthreads();
    if (tid == 0) {
        float gs[NGRP];
        #pragma unroll
        for (int g = 0; g < NGRP; g++) {
            float m1 = -1e30f, m2 = -1e30f;
            #pragma unroll
            for (int j = 0; j < GSZ; j++) {
                float v = sfc[g * GSZ + j];
                if (v > m1) { m2 = m1; m1 = v; }
                else if (v > m2) { m2 = v; }
            }
            gs[g] = m1 + m2;
        }
        bool gsel[NGRP];
        #pragma unroll
        for (int g = 0; g < NGRP; g++) gsel[g] = false;
        for (int r = 0; r < TKG; r++) {
            int b = -1;
            for (int g = 0; g < NGRP; g++)
                if (!gsel[g] && (b < 0 || gs[g] > gs[b])) b = g;
            gsel[b] = true;
        }
        float masked[E_EXP];
        bool used[E_EXP];
        #pragma unroll
        for (int e = 0; e < E_EXP; e++) {
            masked[e] = gsel[e >> 2] ? sfc[e] : 0.0f;
            used[e] = false;
        }
        int idx[TOPK];
        float wsum = 0.f;
        for (int r = 0; r < TOPK; r++) {
            int b = -1;
            for (int e = 0; e < E_EXP; e++)
                if (!used[e] && (b < 0 || masked[e] > masked[b])) b = e;
            used[b] = true;
            idx[r] = b;
            wsum += sc[b];
        }
        float scale = 2.5f / (wsum + 1e-20f);
        for (int r = 0; r < TOPK; r++) {
            g_topk_idx[t * TOPK + r] = idx[r];
            g_topk_w[t * TOPK + r]   = sc[idx[r]] * scale;
        }
    }
}

// ---------------- kernel 2: compaction + work-queue setup ----------------
__global__ __launch_bounds__(1024) void build_lists_kernel()
{
    int e = threadIdx.x >> 5;
    int lane = threadIdx.x & 31;
    int cnt = 0;
    for (int t0 = 0; t0 < T_TOK; t0 += 32) {
        int t = t0 + lane;
        int found = -1;
        #pragma unroll
        for (int k = 0; k < TOPK; k++)
            if (g_topk_idx[t * TOPK + k] == e) found = k;
        unsigned m = __ballot_sync(0xffffffffu, found >= 0);
        if (found >= 0) {
            int pos = cnt + __popc(m & ((1u << lane) - 1));
            g_tok [e * T_TOK + pos] = t;
            g_slot[e * T_TOK + pos] = found;
            g_wt  [e * T_TOK + pos] = g_topk_w[t * TOPK + found];
        }
        cnt += __popc(m);
    }
    if (lane == 0) g_cnt[e] = cnt;
    if (threadIdx.x < E_EXP * 4) g_rdy[threadIdx.x] = 0;
    __syncthreads();
    if (threadIdx.x == 0) {
        int n = 0;
        for (int ee = 0; ee < E_EXP; ee++) {
            int c = g_cnt[ee];
            for (int mt = 0; mt * 64 < c; mt++) g_pairs[n++] = (ee << 2) | mt;
        }
        g_npair = n;
        g_ctr = 0;
    }
}

// ---------------- fused persistent GEMM kernel ----------------
// smem (96KB): A [0,32K): {A0h,A0l,A1h,A1l}@8K; B bf16 single [32K,64K): {BH 16K, BL 16K};
// W fp32 stage double [64K,96K): {S0 16K, S1 16K}
// Per chunk: 2 syncs (store->sync->MMA->wait->sync). Fragment-level padding skip.

__global__ __launch_bounds__(256, 2) void moe_gemm_kernel(
    const float* __restrict__ Wg,
    const float* __restrict__ Wu,
    const float* __restrict__ Wd)
{
    extern __shared__ __align__(128) char dsm[];
    __shared__ int   s_widx;
    __shared__ int   s_toks[64];
    __shared__ int   s_rids[64];
    __shared__ float s_wts[64];

    int tid = threadIdx.x;
    int lane = tid & 31;
    int w = tid >> 5;
    int wm = w & 1;
    int wn = w >> 1;   // 0..3

    uint32_t uA = smem_u32(dsm);
    uint32_t uBh = uA + 32768;
    uint32_t uBl = uA + 49152;
    uint32_t uStage = uA + 65536;

    int arow0 = tid >> 3, aseg = tid & 7;
    int arow1 = arow0 + 32;
    uint32_t dO0 = SWZB((uint32_t)(arow0 * 128 + aseg * 16));
    uint32_t dO1 = SWZB((uint32_t)(arow1 * 128 + aseg * 16));

    // weight staging addressing
    int srow = tid >> 2;            // 0..63 (k-row within chunk)
    int sq4  = (tid & 3) * 16;      // float offset of 64B group within 64-float row
    uint32_t stDstBase = (uint32_t)(srow * 256 + (tid & 3) * 64);

    int aRow = wm * 32 + (lane & 15);
    uint32_t aKb = (uint32_t)((lane >> 4) * 16);
    int bRow = wn * 32 + (lane & 7) + ((lane >> 4) << 3);
    uint32_t bKb = (uint32_t)(((lane >> 3) & 1) * 16);

    int pkb = tid >> 6, pn = tid & 63;
    int lr = lane >> 2, lc = (lane & 3) * 2;

    for (;;) {
        __syncthreads();
        if (tid == 0) s_widx = atomicAdd(&g_ctr, 1);
        __syncthreads();
        int widx = s_widx;
        int npair = g_npair;
        if (widx >= npair * 16) return;

        if (widx < npair * 8) {
            // ================= GATEUP TILE =================
            int pidx = widx >> 3;
            int nt = widx & 7;
            int pr = g_pairs[pidx];
            int e = pr >> 2, mt = pr & 3;
            int ne = g_cnt[e];
            int m0 = mt * 64;

            if (tid < 64) {
                int i = m0 + tid;
                if (i < ne) {
                    int tk = g_tok[e * T_TOK + i];
                    s_toks[tid] = tk;
                    s_rids[tid] = tk * TOPK + g_slot[e * T_TOK + i];
                } else { s_toks[tid] = -1; s_rids[tid] = -1; }
            }
            __syncthreads();

            bool act0 = (m0 + wm * 32) < ne;
            bool act1 = (m0 + wm * 32 + 16) < ne;

            int tokA = s_toks[arow0], tokB = s_toks[arow1];
            const char* sH0 = (const char*)g_xhi + ((size_t)(tokA < 0 ? 0 : tokA) * H_DIM) * 2 + aseg * 16;
            const char* sH1 = (const char*)g_xhi + ((size_t)(tokB < 0 ? 0 : tokB) * H_DIM) * 2 + aseg * 16;
            const char* sL0 = (const char*)g_xlo + ((size_t)(tokA < 0 ? 0 : tokA) * H_DIM) * 2 + aseg * 16;
            const char* sL1 = (const char*)g_xlo + ((size_t)(tokB < 0 ? 0 : tokB) * H_DIM) * 2 + aseg * 16;
            uint32_t szA = (tokA >= 0) ? 16u : 0u;
            uint32_t szB = (tokB >= 0) ? 16u : 0u;

            float acc[2][4][4];
            #pragma unroll
            for (int a = 0; a < 2; a++)
                #pragma unroll
                for (int b = 0; b < 4; b++)
                    #pragma unroll
                    for (int c = 0; c < 4; c++) acc[a][b][c] = 0.f;

            const float* wgB = Wg + (size_t)e * H_DIM * I_DIM + nt * 64;
            const float* wuB = Wu + (size_t)e * H_DIM * I_DIM + nt * 64;
            const float* uSrc = wuB + (size_t)srow * I_DIM + sq4;

            float bw[4][4];
            #pragma unroll
            for (int it = 0; it < 4; it++) {
                const float* p = wgB + (size_t)((pkb + it * 4) * 4) * I_DIM + pn;
                bw[it][0] = p[0]; bw[it][1] = p[I_DIM];
                bw[it][2] = p[2 * I_DIM]; bw[it][3] = p[3 * I_DIM];
            }
            cpa16(uA + dO0, sH0, szA);
            cpa16(uA + dO1, sH1, szB);
            cpa16(uA + 8192 + dO0, sL0, szA);
            cpa16(uA + 8192 + dO1, sL1, szB);
            #pragma unroll
            for (int q = 0; q < 4; q++)
                cpa16(uStage + stDstBase + q * 16, uSrc + q * 4, 16);
            CPA_COMMIT();
            CPA_WAIT0();
            __syncthreads();   // stage(0)/A(0) visible to all

            const int NCH = H_DIM / 64;  // 16
            for (int ch = 0; ch < NCH; ch++) {
                // store phase: g-half from bw regs, u-half from fp32 stage (LDS)
                {
                    const float* stgW = (const float*)(dsm + 65536 + (ch & 1) * 16384);
                    #pragma unroll
                    for (int it = 0; it < 4; it++) {
                        uint32_t h01, l01, h23, l23;
                        bsplit2(bw[it][0], bw[it][1], h01, l01);
                        bsplit2(bw[it][2], bw[it][3], h23, l23);
                        uint32_t o = SWZB((uint32_t)(pn * 128 + (pkb + it * 4) * 8));
                        *(uint2*)(dsm + 32768 + o) = make_uint2(h01, h23);
                        *(uint2*)(dsm + 49152 + o) = make_uint2(l01, l23);
                        int kb4 = (pkb + it * 4) * 4;
                        float c0 = stgW[(kb4 + 0) * 64 + pn];
                        float c1 = stgW[(kb4 + 1) * 64 + pn];
                        float c2 = stgW[(kb4 + 2) * 64 + pn];
                        float c3 = stgW[(kb4 + 3) * 64 + pn];
                        bsplit2(c0, c1, h01, l01);
                        bsplit2(c2, c3, h23, l23);
                        uint32_t o2 = SWZB((uint32_t)((64 + pn) * 128 + (pkb + it * 4) * 8));
                        *(uint2*)(dsm + 32768 + o2) = make_uint2(h01, h23);
                        *(uint2*)(dsm + 49152 + o2) = make_uint2(l01, l23);
                    }
                }
                __syncthreads();   // B ready

                if (ch + 1 < NCH) {
                    uint32_t ab = uA + (uint32_t)(((ch + 1) & 1) * 16384);
                    uint32_t boff = (uint32_t)((ch + 1) * 128);
                    cpa16(ab + dO0, sH0 + boff, szA);
                    cpa16(ab + dO1, sH1 + boff, szB);
                    cpa16(ab + 8192 + dO0, sL0 + boff, szA);
                    cpa16(ab + 8192 + dO1, sL1 + boff, szB);
                    uint32_t sb = uStage + (uint32_t)(((ch + 1) & 1) * 16384);
                    const float* us = uSrc + (size_t)(ch + 1) * 64 * I_DIM;
                    #pragma unroll
                    for (int q = 0; q < 4; q++)
                        cpa16(sb + stDstBase + q * 16, us + q * 4, 16);
                    CPA_COMMIT();
                    int k0n = (ch + 1) * 64;
                    #pragma unroll
                    for (int it = 0; it < 4; it++) {
                        const float* p = wgB + (size_t)(k0n + (pkb + it * 4) * 4) * I_DIM + pn;
                        bw[it][0] = p[0]; bw[it][1] = p[I_DIM];
                        bw[it][2] = p[2 * I_DIM]; bw[it][3] = p[3 * I_DIM];
                    }
                }

                if (act0) {
                    uint32_t uAhi = uA + (uint32_t)((ch & 1) * 16384);
                    uint32_t uAlo = uAhi + 8192;
                    #pragma unroll
                    for (int ks = 0; ks < 4; ks++) {
                        uint32_t ah[2][4], al[2][4];
                        {
                            uint32_t o = SWZB((uint32_t)(aRow * 128) + (uint32_t)(ks * 32) + aKb);
                            ldm4(ah[0], uAhi + o);
                            ldm4(al[0], uAlo + o);
                        }
                        if (act1) {
                            uint32_t o = SWZB((uint32_t)((aRow + 16) * 128) + (uint32_t)(ks * 32) + aKb);
                            ldm4(ah[1], uAhi + o);
                            ldm4(al[1], uAlo + o);
                        }
                        uint32_t ob1 = SWZB((uint32_t)(bRow * 128) + (uint32_t)(ks * 32) + bKb);
                        uint32_t ob2 = SWZB((uint32_t)((bRow + 16) * 128) + (uint32_t)(ks * 32) + bKb);
                        uint32_t bh[8], bl[8];
                        ldm4(bh, uBh + ob1);
                        ldm4(bh + 4, uBh + ob2);
                        ldm4(bl, uBl + ob1);
                        ldm4(bl + 4, uBl + ob2);
                        #pragma unroll
                        for (int nf = 0; nf < 4; nf++) {
                            mma16816(acc[0][nf], ah[0], bh[nf * 2], bh[nf * 2 + 1]);
                            mma16816(acc[0][nf], ah[0], bl[nf * 2], bl[nf * 2 + 1]);
                            mma16816(acc[0][nf], al[0], bh[nf * 2], bh[nf * 2 + 1]);
                        }
                        if (act1) {
                            #pragma unroll
                            for (int nf = 0; nf < 4; nf++) {
                                mma16816(acc[1][nf], ah[1], bh[nf * 2], bh[nf * 2 + 1]);
                                mma16816(acc[1][nf], ah[1], bl[nf * 2], bl[nf * 2 + 1]);
                                mma16816(acc[1][nf], al[1], bh[nf * 2], bh[nf * 2 + 1]);
                            }
                        }
                    }
                }
                CPA_WAIT0();       // next A/stage landed (hidden under MMA)
                __syncthreads();   // visibility + protect B/A buffers
            }

            // epilogue: stage to smem, a = silu(g)*u, write bf16 hi/lo
            float* stg = (float*)dsm;
            #pragma unroll
            for (int mf = 0; mf < 2; mf++) {
                #pragma unroll
                for (int nf = 0; nf < 4; nf++) {
                    int col = wn * 32 + nf * 8 + lc;   // 0..63 g, 64..127 u
                    #pragma unroll
                    for (int half = 0; half < 2; half++) {
                        int row = wm * 32 + mf * 16 + lr + half * 8;
                        *(float2*)&stg[row * 128 + col] =
                            make_float2(acc[mf][nf][half * 2], acc[mf][nf][half * 2 + 1]);
                    }
                }
            }
            __syncthreads();
            #pragma unroll
            for (int p = 0; p < 8; p++) {
                int idx2 = tid + p * 256;
                int row = idx2 >> 5;
                int cp = idx2 & 31;
                int rid = s_rids[row];
                if (rid >= 0) {
                    float2 g = *(float2*)&stg[row * 128 + cp * 2];
                    float2 u = *(float2*)&stg[row * 128 + 64 + cp * 2];
                    float a0 = (g.x / (1.f + expf(-g.x))) * u.x;
                    float a1 = (g.y / (1.f + expf(-g.y))) * u.y;
                    uint32_t h, l;
                    bsplit2(a0, a1, h, l);
                    size_t off = (size_t)rid * I_DIM + nt * 64 + cp * 2;
                    *(uint32_t*)(g_ahi + off) = h;
                    *(uint32_t*)(g_alo + off) = l;
                }
            }
            __threadfence();
            __syncthreads();
            if (tid == 0) atomicAdd(&g_rdy[pidx], 1);
        } else {
            // ================= DOWN TILE =================
            int w2 = widx - npair * 8;
            int pidx = w2 >> 3;
            int nt = w2 & 7;
            int pr = g_pairs[pidx];
            int e = pr >> 2, mt = pr & 3;
            int ne = g_cnt[e];
            int m0 = mt * 64;

            if (tid == 0) {
                while (atomicAdd(&g_rdy[pidx], 0) < 8) { }
            }
            __syncthreads();

            if (tid < 64) {
                int i = m0 + tid;
                if (i < ne) {
                    int tk = g_tok[e * T_TOK + i];
                    s_rids[tid] = tk * TOPK + g_slot[e * T_TOK + i];
                    s_wts[tid]  = g_wt[e * T_TOK + i];
                } else { s_rids[tid] = -1; s_wts[tid] = 0.f; }
            }
            __syncthreads();

            bool act0 = (m0 + wm * 32) < ne;
            bool act1 = (m0 + wm * 32 + 16) < ne;

            int ridA = s_rids[arow0], ridB = s_rids[arow1];
            const char* sH0 = (const char*)g_ahi + ((size_t)(ridA < 0 ? 0 : ridA) * I_DIM) * 2 + aseg * 16;
            const char* sH1 = (const char*)g_ahi + ((size_t)(ridB < 0 ? 0 : ridB) * I_DIM) * 2 + aseg * 16;
            const char* sL0 = (const char*)g_alo + ((size_t)(ridA < 0 ? 0 : ridA) * I_DIM) * 2 + aseg * 16;
            const char* sL1 = (const char*)g_alo + ((size_t)(ridB < 0 ? 0 : ridB) * I_DIM) * 2 + aseg * 16;
            uint32_t szA = (ridA >= 0) ? 16u : 0u;
            uint32_t szB = (ridB >= 0) ? 16u : 0u;

            float acc[2][4][4];
            #pragma unroll
            for (int a = 0; a < 2; a++)
                #pragma unroll
                for (int b = 0; b < 4; b++)
                    #pragma unroll
                    for (int c = 0; c < 4; c++) acc[a][b][c] = 0.f;

            const float* wdB = Wd + (size_t)e * I_DIM * H_DIM + nt * 128;
            const float* uSrc = wdB + 64 + (size_t)srow * H_DIM + sq4;
            float bw[4][4];
            #pragma unroll
            for (int it = 0; it < 4; it++) {
                const float* p = wdB + (size_t)((pkb + it * 4) * 4) * H_DIM + pn;
                bw[it][0] = p[0]; bw[it][1] = p[H_DIM];
                bw[it][2] = p[2 * H_DIM]; bw[it][3] = p[3 * H_DIM];
            }
            cpa16(uA + dO0, sH0, szA);
            cpa16(uA + dO1, sH1, szB);
            cpa16(uA + 8192 + dO0, sL0, szA);
            cpa16(uA + 8192 + dO1, sL1, szB);
            #pragma unroll
            for (int q = 0; q < 4; q++)
                cpa16(uStage + stDstBase + q * 16, uSrc + q * 4, 16);
            CPA_COMMIT();
            CPA_WAIT0();
            __syncthreads();

            const int NCH = I_DIM / 64;  // 8
            for (int ch = 0; ch < NCH; ch++) {
                {
                    const float* stgW = (const float*)(dsm + 65536 + (ch & 1) * 16384);
                    #pragma unroll
                    for (int it = 0; it < 4; it++) {
                        uint32_t h01, l01, h23, l23;
                        bsplit2(bw[it][0], bw[it][1], h01, l01);
                        bsplit2(bw[it][2], bw[it][3], h23, l23);
                        uint32_t o = SWZB((uint32_t)(pn * 128 + (pkb + it * 4) * 8));
                        *(uint2*)(dsm + 32768 + o) = make_uint2(h01, h23);
                        *(uint2*)(dsm + 49152 + o) = make_uint2(l01, l23);
                        int kb4 = (pkb + it * 4) * 4;
                        float c0 = stgW[(kb4 + 0) * 64 + pn];
                        float c1 = stgW[(kb4 + 1) * 64 + pn];
                        float c2 = stgW[(kb4 + 2) * 64 + pn];
                        float c3 = stgW[(kb4 + 3) * 64 + pn];
                        bsplit2(c0, c1, h01, l01);
                        bsplit2(c2, c3, h23, l23);
                        uint32_t o2 = SWZB((uint32_t)((64 + pn) * 128 + (pkb + it * 4) * 8));
                        *(uint2*)(dsm + 32768 + o2) = make_uint2(h01, h23);
                        *(uint2*)(dsm + 49152 + o2) = make_uint2(l01, l23);
                    }
                }
                __syncthreads();

                if (ch + 1 < NCH) {
                    uint32_t ab = uA + (uint32_t)(((ch + 1) & 1) * 16384);
                    uint32_t boff = (uint32_t)((ch + 1) * 128);
                    cpa16(ab + dO0, sH0 + boff, szA);
                    cpa16(ab + dO1, sH1 + boff, szB);
                    cpa16(ab + 8192 + dO0, sL0 + boff, szA);
                    cpa16(ab + 8192 + dO1, sL1 + boff, szB);
                    uint32_t sb = uStage + (uint32_t)(((ch + 1) & 1) * 16384);
                    const float* us = uSrc + (size_t)(ch + 1) * 64 * H_DIM;
                    #pragma unroll
                    for (int q = 0; q < 4; q++)
                        cpa16(sb + stDstBase + q * 16, us + q * 4, 16);
                    CPA_COMMIT();
                    int k0n = (ch + 1) * 64;
                    #pragma unroll
                    for (int it = 0; it < 4; it++) {
                        const float* p = wdB + (size_t)(k0n + (pkb + it * 4) * 4) * H_DIM + pn;
                        bw[it][0] = p[0]; bw[it][1] = p[H_DIM];
                        bw[it][2] = p[2 * H_DIM]; bw[it][3] = p[3 * H_DIM];
                    }
                }

                if (act0) {
                    uint32_t uAhi = uA + (uint32_t)((ch & 1) * 16384);
                    uint32_t uAlo = uAhi + 8192;
                    #pragma unroll
                    for (int ks = 0; ks < 4; ks++) {
                        uint32_t ah[2][4], al[2][4];
                        {
                            uint32_t o = SWZB((uint32_t)(aRow * 128) + (uint32_t)(ks * 32) + aKb);
                            ldm4(ah[0], uAhi + o);
                            ldm4(al[0], uAlo + o);
                        }
                        if (act1) {
                            uint32_t o = SWZB((uint32_t)((aRow + 16) * 128) + (uint32_t)(ks * 32) + aKb);
                            ldm4(ah[1], uAhi + o);
                            ldm4(al[1], uAlo + o);
                        }
                        uint32_t ob1 = SWZB((uint32_t)(bRow * 128) + (uint32_t)(ks * 32) + bKb);
                        uint32_t ob2 = SWZB((uint32_t)((bRow + 16) * 128) + (uint32_t)(ks * 32) + bKb);
                        uint32_t bh[8], bl[8];
                        ldm4(bh, uBh + ob1);
                        ldm4(bh + 4, uBh + ob2);
                        ldm4(bl, uBl + ob1);
                        ldm4(bl + 4, uBl + ob2);
                        #pragma unroll
                        for (int nf = 0; nf < 4; nf++) {
                            mma16816(acc[0][nf], ah[0], bh[nf * 2], bh[nf * 2 + 1]);
                            mma16816(acc[0][nf], ah[0], bl[nf * 2], bl[nf * 2 + 1]);
                            mma16816(acc[0][nf], al[0], bh[nf * 2], bh[nf * 2 + 1]);
                        }
                        if (act1) {
                            #pragma unroll
                            for (int nf = 0; nf < 4; nf++) {
                                mma16816(acc[1][nf], ah[1], bh[nf * 2], bh[nf * 2 + 1]);
                                mma16816(acc[1][nf], ah[1], bl[nf * 2], bl[nf * 2 + 1]);
                                mma16816(acc[1][nf], al[1], bh[nf * 2], bh[nf * 2 + 1]);
                            }
                        }
                    }
                }
                CPA_WAIT0();
                __syncthreads();
            }

            #pragma unroll
            for (int mf = 0; mf < 2; mf++) {
                #pragma unroll
                for (int nf = 0; nf < 4; nf++) {
                    int col = nt * 128 + wn * 32 + nf * 8 + lc;
                    #pragma unroll
                    for (int half = 0; half < 2; half++) {
                        int row = wm * 32 + mf * 16 + lr + half * 8;
                        if (m0 + row < ne) {
                            int rid = s_rids[row];
                            float wt = s_wts[row];
                            float2 o;
                            o.x = wt * acc[mf][nf][half * 2 + 0];
                            o.y = wt * acc[mf][nf][half * 2 + 1];
                            *(float2*)(g_ybuf + (size_t)rid * H_DIM + col) = o;
                        }
                    }
                }
            }
        }
    }
}

// ---------------- kernel: deterministic combine ----------------
__global__ __launch_bounds__(256) void combine_kernel(float* __restrict__ out)
{
    int idx = blockIdx.x * 256 + threadIdx.x;
    int t = idx >> 10;
    int h = idx & 1023;
    float s = 0.f;
    #pragma unroll
    for (int k = 0; k < TOPK; k++)
        s += g_ybuf[((size_t)t * TOPK + k) * H_DIM + h];
    out[idx] = s;
}

// ---------------- launch ----------------
#define GEMM_SMEM (32768 + 32768 + 32768)   // 96KB
#define N_PERSIST 296

extern "C" void kernel_launch(void* const* d_in, const int* in_sizes, int n_in,
                              void* d_out, int out_size)
{
    const float* x      = (const float*)d_in[0];
    const float* gate_w = (const float*)d_in[1];
    const float* bias   = (const float*)d_in[2];
    const float* Wg     = (const float*)d_in[3];
    const float* Wu     = (const float*)d_in[4];
    const float* Wd     = (const float*)d_in[5];
    float* out = (float*)d_out;

    cudaFuncSetAttribute(moe_gemm_kernel, cudaFuncAttributeMaxDynamicSharedMemorySize, GEMM_SMEM);

    routing_kernel<<<T_TOK, 128>>>(x, gate_w, bias);
    build_lists_kernel<<<1, 1024>>>();
    moe_gemm_kernel<<<N_PERSIST, 256, GEMM_SMEM>>>(Wg, Wu, Wd);
    combine_kernel<<<(T_TOK * H_DIM) / 256, 256>>>(out);
}

// round 13
// speedup vs baseline: 1.1163x; 1.1163x over previous
#include <cuda_runtime.h>
#include <cuda_bf16.h>
#include <math.h>
#include <stdint.h>

#define T_TOK 256
#define H_DIM 1024
#define I_DIM 512
#define E_EXP 32
#define TOPK  8
#define NGRP  8
#define GSZ   4
#define TKG   4

#define SWZB(o) ((o) ^ (((o) >> 3) & 0x70))

// ---------------- helpers ----------------
__device__ __forceinline__ uint32_t smem_u32(const void* p) {
    uint32_t a;
    asm("{ .reg .u64 t; cvta.to.shared.u64 t, %1; cvt.u32.u64 %0, t; }" : "=r"(a) : "l"(p));
    return a;
}

// split 2 fp32 -> packed bf16x2 hi + bf16x2 lo (lo = exact residual)
__device__ __forceinline__ void bsplit2(float e0, float e1, uint32_t &h, uint32_t &l) {
    asm("cvt.rn.bf16x2.f32 %0, %1, %2;" : "=r"(h) : "f"(e1), "f"(e0));
    float f0 = __uint_as_float(h << 16);
    float f1 = __uint_as_float(h & 0xFFFF0000u);
    float r0 = e0 - f0, r1 = e1 - f1;
    asm("cvt.rn.bf16x2.f32 %0, %1, %2;" : "=r"(l) : "f"(r1), "f"(r0));
}

__device__ __forceinline__ void ldm4(uint32_t r[4], uint32_t addr) {
    asm volatile("ldmatrix.sync.aligned.m8n8.x4.shared.b16 {%0,%1,%2,%3}, [%4];"
        : "=r"(r[0]), "=r"(r[1]), "=r"(r[2]), "=r"(r[3]) : "r"(addr));
}

__device__ __forceinline__ void mma16816(float d[4], const uint32_t a[4],
                                         uint32_t b0, uint32_t b1) {
    asm volatile("mma.sync.aligned.m16n8k16.row.col.f32.bf16.bf16.f32 "
        "{%0,%1,%2,%3}, {%4,%5,%6,%7}, {%8,%9}, {%0,%1,%2,%3};"
        : "+f"(d[0]), "+f"(d[1]), "+f"(d[2]), "+f"(d[3])
        : "r"(a[0]), "r"(a[1]), "r"(a[2]), "r"(a[3]), "r"(b0), "r"(b1));
}

__device__ __forceinline__ void cpa16(uint32_t dst, const void* src, uint32_t sz) {
    asm volatile("cp.async.cg.shared.global [%0], [%1], 16, %2;"
        :: "r"(dst), "l"(src), "r"(sz) : "memory");
}
#define CPA_COMMIT() asm volatile("cp.async.commit_group;" ::: "memory")
#define CPA_WAIT0()  asm volatile("cp.async.wait_group 0;" ::: "memory")

// ---------------- device scratch ----------------
__device__ int   g_topk_idx[T_TOK * TOPK];
__device__ float g_topk_w[T_TOK * TOPK];
__device__ int   g_cnt[E_EXP];
__device__ int   g_tok[E_EXP * T_TOK];
__device__ int   g_slot[E_EXP * T_TOK];
__device__ float g_wt[E_EXP * T_TOK];
__device__ uint16_t g_xhi[T_TOK * H_DIM];
__device__ uint16_t g_xlo[T_TOK * H_DIM];
__device__ uint16_t g_ahi[T_TOK * TOPK * I_DIM];
__device__ uint16_t g_alo[T_TOK * TOPK * I_DIM];
__device__ float g_ybuf[T_TOK * TOPK * H_DIM];

// work queue
__device__ int g_pairs[E_EXP * 4];   // (e<<2)|mt
__device__ int g_npair;
__device__ int g_ctr;
__device__ int g_rdy[E_EXP * 4];     // per-pair gateup completion count (target 8)

// ---------------- kernel 1: routing (coalesced GEMV + fused x split) ----------------
__global__ __launch_bounds__(128) void routing_kernel(
    const float* __restrict__ x, const float* __restrict__ gate_w,
    const float* __restrict__ bias)
{
    int t = blockIdx.x;
    __shared__ float xs[H_DIM];
    __shared__ float part[4][E_EXP];
    __shared__ float sc[E_EXP];
    __shared__ float sfc[E_EXP];
    int tid = threadIdx.x;
    for (int i = tid; i < H_DIM / 4; i += 128) {
        float4 v = *(const float4*)(x + (size_t)t * H_DIM + i * 4);
        *(float4*)&xs[i * 4] = v;
        uint32_t h0, l0, h1, l1;
        bsplit2(v.x, v.y, h0, l0);
        bsplit2(v.z, v.w, h1, l1);
        ((uint2*)(g_xhi + (size_t)t * H_DIM))[i] = make_uint2(h0, h1);
        ((uint2*)(g_xlo + (size_t)t * H_DIM))[i] = make_uint2(l0, l1);
    }
    __syncthreads();
    int warp = tid >> 5, lane = tid & 31;
    {
        float s = 0.f;
        const float* gw = gate_w + lane;
        int h0 = warp * (H_DIM / 4);
        #pragma unroll 4
        for (int h = h0; h < h0 + H_DIM / 4; h++)
            s += xs[h] * gw[(size_t)h * E_EXP];
        part[warp][lane] = s;
    }
    __syncthreads();
    if (tid < E_EXP) {
        float s = part[0][tid] + part[1][tid] + part[2][tid] + part[3][tid];
        float sig = 1.f / (1.f + expf(-s));
        sc[tid] = sig;
        sfc[tid] = sig + bias[tid];
    }
    __syncthreads();
    if (tid == 0) {
        float gs[NGRP];
        #pragma unroll
        for (int g = 0; g < NGRP; g++) {
            float m1 = -1e30f, m2 = -1e30f;
            #pragma unroll
            for (int j = 0; j < GSZ; j++) {
                float v = sfc[g * GSZ + j];
                if (v > m1) { m2 = m1; m1 = v; }
                else if (v > m2) { m2 = v; }
            }
            gs[g] = m1 + m2;
        }
        bool gsel[NGRP];
        #pragma unroll
        for (int g = 0; g < NGRP; g++) gsel[g] = false;
        for (int r = 0; r < TKG; r++) {
            int b = -1;
            for (int g = 0; g < NGRP; g++)
                if (!gsel[g] && (b < 0 || gs[g] > gs[b])) b = g;
            gsel[b] = true;
        }
        float masked[E_EXP];
        bool used[E_EXP];
        #pragma unroll
        for (int e = 0; e < E_EXP; e++) {
            masked[e] = gsel[e >> 2] ? sfc[e] : 0.0f;
            used[e] = false;
        }
        int idx[TOPK];
        float wsum = 0.f;
        for (int r = 0; r < TOPK; r++) {
            int b = -1;
            for (int e = 0; e < E_EXP; e++)
                if (!used[e] && (b < 0 || masked[e] > masked[b])) b = e;
            used[b] = true;
            idx[r] = b;
            wsum += sc[b];
        }
        float scale = 2.5f / (wsum + 1e-20f);
        for (int r = 0; r < TOPK; r++) {
            g_topk_idx[t * TOPK + r] = idx[r];
            g_topk_w[t * TOPK + r]   = sc[idx[r]] * scale;
        }
    }
}

// ---------------- kernel 2: compaction + work-queue setup ----------------
__global__ __launch_bounds__(1024) void build_lists_kernel()
{
    int e = threadIdx.x >> 5;
    int lane = threadIdx.x & 31;
    int cnt = 0;
    for (int t0 = 0; t0 < T_TOK; t0 += 32) {
        int t = t0 + lane;
        int found = -1;
        #pragma unroll
        for (int k = 0; k < TOPK; k++)
            if (g_topk_idx[t * TOPK + k] == e) found = k;
        unsigned m = __ballot_sync(0xffffffffu, found >= 0);
        if (found >= 0) {
            int pos = cnt + __popc(m & ((1u << lane) - 1));
            g_tok [e * T_TOK + pos] = t;
            g_slot[e * T_TOK + pos] = found;
            g_wt  [e * T_TOK + pos] = g_topk_w[t * TOPK + found];
        }
        cnt += __popc(m);
    }
    if (lane == 0) g_cnt[e] = cnt;
    if (threadIdx.x < E_EXP * 4) g_rdy[threadIdx.x] = 0;
    __syncthreads();
    if (threadIdx.x == 0) {
        int n = 0;
        for (int ee = 0; ee < E_EXP; ee++) {
            int c = g_cnt[ee];
            for (int mt = 0; mt * 64 < c; mt++) g_pairs[n++] = (ee << 2) | mt;
        }
        g_npair = n;
        g_ctr = 0;
    }
}

// ---------------- fused persistent GEMM kernel (exact R10 structure) ----------------
// smem (96KB): A [0,32K): {A0h,A0l,A1h,A1l}@8K; B bf16 single [32K,64K): {BH 16K, BL 16K};
// W fp32 stage double [64K,96K): {S0 16K, S1 16K}

__global__ __launch_bounds__(256, 2) void moe_gemm_kernel(
    const float* __restrict__ Wg,
    const float* __restrict__ Wu,
    const float* __restrict__ Wd)
{
    extern __shared__ __align__(128) char dsm[];
    __shared__ int   s_widx;
    __shared__ int   s_toks[64];
    __shared__ int   s_rids[64];
    __shared__ float s_wts[64];

    int tid = threadIdx.x;
    int lane = tid & 31;
    int w = tid >> 5;
    int wm = w & 1;
    int wn = w >> 1;   // 0..3

    uint32_t uA = smem_u32(dsm);
    uint32_t uBh = uA + 32768;
    uint32_t uBl = uA + 49152;
    uint32_t uStage = uA + 65536;

    int arow0 = tid >> 3, aseg = tid & 7;
    int arow1 = arow0 + 32;
    uint32_t dO0 = SWZB((uint32_t)(arow0 * 128 + aseg * 16));
    uint32_t dO1 = SWZB((uint32_t)(arow1 * 128 + aseg * 16));

    // weight staging addressing
    int srow = tid >> 2;            // 0..63 (k-row within chunk)
    int sq4  = (tid & 3) * 16;      // float offset of 64B group within 64-float row
    uint32_t stDstBase = (uint32_t)(srow * 256 + (tid & 3) * 64);

    int aRow = wm * 32 + (lane & 15);
    uint32_t aKb = (uint32_t)((lane >> 4) * 16);
    int bRow = wn * 32 + (lane & 7) + ((lane >> 4) << 3);
    uint32_t bKb = (uint32_t)(((lane >> 3) & 1) * 16);

    int pkb = tid >> 6, pn = tid & 63;
    int lr = lane >> 2, lc = (lane & 3) * 2;

    for (;;) {
        __syncthreads();
        if (tid == 0) s_widx = atomicAdd(&g_ctr, 1);
        __syncthreads();
        int widx = s_widx;
        int npair = g_npair;
        if (widx >= npair * 16) return;

        if (widx < npair * 8) {
            // ================= GATEUP TILE =================
            int pidx = widx >> 3;
            int nt = widx & 7;
            int pr = g_pairs[pidx];
            int e = pr >> 2, mt = pr & 3;
            int ne = g_cnt[e];
            int m0 = mt * 64;

            if (tid < 64) {
                int i = m0 + tid;
                if (i < ne) {
                    int tk = g_tok[e * T_TOK + i];
                    s_toks[tid] = tk;
                    s_rids[tid] = tk * TOPK + g_slot[e * T_TOK + i];
                } else { s_toks[tid] = -1; s_rids[tid] = -1; }
            }
            __syncthreads();

            int tokA = s_toks[arow0], tokB = s_toks[arow1];
            const char* sH0 = (const char*)g_xhi + ((size_t)(tokA < 0 ? 0 : tokA) * H_DIM) * 2 + aseg * 16;
            const char* sH1 = (const char*)g_xhi + ((size_t)(tokB < 0 ? 0 : tokB) * H_DIM) * 2 + aseg * 16;
            const char* sL0 = (const char*)g_xlo + ((size_t)(tokA < 0 ? 0 : tokA) * H_DIM) * 2 + aseg * 16;
            const char* sL1 = (const char*)g_xlo + ((size_t)(tokB < 0 ? 0 : tokB) * H_DIM) * 2 + aseg * 16;
            uint32_t szA = (tokA >= 0) ? 16u : 0u;
            uint32_t szB = (tokB >= 0) ? 16u : 0u;

            float acc[2][4][4];
            #pragma unroll
            for (int a = 0; a < 2; a++)
                #pragma unroll
                for (int b = 0; b < 4; b++)
                    #pragma unroll
                    for (int c = 0; c < 4; c++) acc[a][b][c] = 0.f;

            const float* wgB = Wg + (size_t)e * H_DIM * I_DIM + nt * 64;
            const float* wuB = Wu + (size_t)e * H_DIM * I_DIM + nt * 64;
            const float* uSrc = wuB + (size_t)srow * I_DIM + sq4;

            float bw[4][4];
            #pragma unroll
            for (int it = 0; it < 4; it++) {
                const float* p = wgB + (size_t)((pkb + it * 4) * 4) * I_DIM + pn;
                bw[it][0] = p[0]; bw[it][1] = p[I_DIM];
                bw[it][2] = p[2 * I_DIM]; bw[it][3] = p[3 * I_DIM];
            }
            cpa16(uA + dO0, sH0, szA);
            cpa16(uA + dO1, sH1, szB);
            cpa16(uA + 8192 + dO0, sL0, szA);
            cpa16(uA + 8192 + dO1, sL1, szB);
            #pragma unroll
            for (int q = 0; q < 4; q++)
                cpa16(uStage + stDstBase + q * 16, uSrc + q * 4, 16);
            CPA_COMMIT();

            const int NCH = H_DIM / 64;  // 16
            for (int ch = 0; ch < NCH; ch++) {
                CPA_WAIT0();
                __syncthreads();   // make ALL threads' cp.async data visible before stage reads
                // store phase: g-half from bw regs, u-half from fp32 stage (LDS)
                {
                    const float* stgW = (const float*)(dsm + 65536 + (ch & 1) * 16384);
                    #pragma unroll
                    for (int it = 0; it < 4; it++) {
                        uint32_t h01, l01, h23, l23;
                        bsplit2(bw[it][0], bw[it][1], h01, l01);
                        bsplit2(bw[it][2], bw[it][3], h23, l23);
                        uint32_t o = SWZB((uint32_t)(pn * 128 + (pkb + it * 4) * 8));
                        *(uint2*)(dsm + 32768 + o) = make_uint2(h01, h23);
                        *(uint2*)(dsm + 49152 + o) = make_uint2(l01, l23);
                        int kb4 = (pkb + it * 4) * 4;
                        float c0 = stgW[(kb4 + 0) * 64 + pn];
                        float c1 = stgW[(kb4 + 1) * 64 + pn];
                        float c2 = stgW[(kb4 + 2) * 64 + pn];
                        float c3 = stgW[(kb4 + 3) * 64 + pn];
                        bsplit2(c0, c1, h01, l01);
                        bsplit2(c2, c3, h23, l23);
                        uint32_t o2 = SWZB((uint32_t)((64 + pn) * 128 + (pkb + it * 4) * 8));
                        *(uint2*)(dsm + 32768 + o2) = make_uint2(h01, h23);
                        *(uint2*)(dsm + 49152 + o2) = make_uint2(l01, l23);
                    }
                }
                __syncthreads();

                if (ch + 1 < NCH) {
                    uint32_t ab = uA + (uint32_t)(((ch + 1) & 1) * 16384);
                    uint32_t boff = (uint32_t)((ch + 1) * 128);
                    cpa16(ab + dO0, sH0 + boff, szA);
                    cpa16(ab + dO1, sH1 + boff, szB);
                    cpa16(ab + 8192 + dO0, sL0 + boff, szA);
                    cpa16(ab + 8192 + dO1, sL1 + boff, szB);
                    uint32_t sb = uStage + (uint32_t)(((ch + 1) & 1) * 16384);
                    const float* us = uSrc + (size_t)(ch + 1) * 64 * I_DIM;
                    #pragma unroll
                    for (int q = 0; q < 4; q++)
                        cpa16(sb + stDstBase + q * 16, us + q * 4, 16);
                    CPA_COMMIT();
                    int k0n = (ch + 1) * 64;
                    #pragma unroll
                    for (int it = 0; it < 4; it++) {
                        const float* p = wgB + (size_t)(k0n + (pkb + it * 4) * 4) * I_DIM + pn;
                        bw[it][0] = p[0]; bw[it][1] = p[I_DIM];
                        bw[it][2] = p[2 * I_DIM]; bw[it][3] = p[3 * I_DIM];
                    }
                }

                uint32_t uAhi = uA + (uint32_t)((ch & 1) * 16384);
                uint32_t uAlo = uAhi + 8192;
                #pragma unroll
                for (int ks = 0; ks < 4; ks++) {
                    uint32_t ah[2][4], al[2][4];
                    #pragma unroll
                    for (int mf = 0; mf < 2; mf++) {
                        uint32_t o = SWZB((uint32_t)((aRow + mf * 16) * 128) + (uint32_t)(ks * 32) + aKb);
                        ldm4(ah[mf], uAhi + o);
                        ldm4(al[mf], uAlo + o);
                    }
                    uint32_t ob1 = SWZB((uint32_t)(bRow * 128) + (uint32_t)(ks * 32) + bKb);
                    uint32_t ob2 = SWZB((uint32_t)((bRow + 16) * 128) + (uint32_t)(ks * 32) + bKb);
                    uint32_t bh[8], bl[8];
                    ldm4(bh, uBh + ob1);
                    ldm4(bh + 4, uBh + ob2);
                    ldm4(bl, uBl + ob1);
                    ldm4(bl + 4, uBl + ob2);
                    #pragma unroll
                    for (int mf = 0; mf < 2; mf++) {
                        #pragma unroll
                        for (int nf = 0; nf < 4; nf++) {
                            mma16816(acc[mf][nf], ah[mf], bh[nf * 2], bh[nf * 2 + 1]);
                            mma16816(acc[mf][nf], ah[mf], bl[nf * 2], bl[nf * 2 + 1]);
                            mma16816(acc[mf][nf], al[mf], bh[nf * 2], bh[nf * 2 + 1]);
                        }
                    }
                }
                __syncthreads();   // protect single B buffer before next store
            }

            // epilogue: stage accs to smem, a = silu(g)*u, write bf16 hi/lo
            float* stg = (float*)dsm;
            #pragma unroll
            for (int mf = 0; mf < 2; mf++) {
                #pragma unroll
                for (int nf = 0; nf < 4; nf++) {
                    int col = wn * 32 + nf * 8 + lc;
                    #pragma unroll
                    for (int half = 0; half < 2; half++) {
                        int row = wm * 32 + mf * 16 + lr + half * 8;
                        *(float2*)&stg[row * 128 + col] =
                            make_float2(acc[mf][nf][half * 2], acc[mf][nf][half * 2 + 1]);
                    }
                }
            }
            __syncthreads();
            #pragma unroll
            for (int p = 0; p < 8; p++) {
                int idx2 = tid + p * 256;
                int row = idx2 >> 5;
                int cp = idx2 & 31;
                int rid = s_rids[row];
                if (rid >= 0) {
                    float2 g = *(float2*)&stg[row * 128 + cp * 2];
                    float2 u = *(float2*)&stg[row * 128 + 64 + cp * 2];
                    float a0 = (g.x / (1.f + expf(-g.x))) * u.x;
                    float a1 = (g.y / (1.f + expf(-g.y))) * u.y;
                    uint32_t h, l;
                    bsplit2(a0, a1, h, l);
                    size_t off = (size_t)rid * I_DIM + nt * 64 + cp * 2;
                    *(uint32_t*)(g_ahi + off) = h;
                    *(uint32_t*)(g_alo + off) = l;
                }
            }
            __threadfence();
            __syncthreads();
            if (tid == 0) atomicAdd(&g_rdy[pidx], 1);
        } else {
            // ================= DOWN TILE =================
            int w2 = widx - npair * 8;
            int pidx = w2 >> 3;
            int nt = w2 & 7;
            int pr = g_pairs[pidx];
            int e = pr >> 2, mt = pr & 3;
            int ne = g_cnt[e];
            int m0 = mt * 64;

            if (tid == 0) {
                while (atomicAdd(&g_rdy[pidx], 0) < 8) { }
            }
            __syncthreads();

            if (tid < 64) {
                int i = m0 + tid;
                if (i < ne) {
                    int tk = g_tok[e * T_TOK + i];
                    s_rids[tid] = tk * TOPK + g_slot[e * T_TOK + i];
                    s_wts[tid]  = g_wt[e * T_TOK + i];
                } else { s_rids[tid] = -1; s_wts[tid] = 0.f; }
            }
            __syncthreads();

            int ridA = s_rids[arow0], ridB = s_rids[arow1];
            const char* sH0 = (const char*)g_ahi + ((size_t)(ridA < 0 ? 0 : ridA) * I_DIM) * 2 + aseg * 16;
            const char* sH1 = (const char*)g_ahi + ((size_t)(ridB < 0 ? 0 : ridB) * I_DIM) * 2 + aseg * 16;
            const char* sL0 = (const char*)g_alo + ((size_t)(ridA < 0 ? 0 : ridA) * I_DIM) * 2 + aseg * 16;
            const char* sL1 = (const char*)g_alo + ((size_t)(ridB < 0 ? 0 : ridB) * I_DIM) * 2 + aseg * 16;
            uint32_t szA = (ridA >= 0) ? 16u : 0u;
            uint32_t szB = (ridB >= 0) ? 16u : 0u;

            float acc[2][4][4];
            #pragma unroll
            for (int a = 0; a < 2; a++)
                #pragma unroll
                for (int b = 0; b < 4; b++)
                    #pragma unroll
                    for (int c = 0; c < 4; c++) acc[a][b][c] = 0.f;

            const float* wdB = Wd + (size_t)e * I_DIM * H_DIM + nt * 128;
            const float* uSrc = wdB + 64 + (size_t)srow * H_DIM + sq4;
            float bw[4][4];
            #pragma unroll
            for (int it = 0; it < 4; it++) {
                const float* p = wdB + (size_t)((pkb + it * 4) * 4) * H_DIM + pn;
                bw[it][0] = p[0]; bw[it][1] = p[H_DIM];
                bw[it][2] = p[2 * H_DIM]; bw[it][3] = p[3 * H_DIM];
            }
            cpa16(uA + dO0, sH0, szA);
            cpa16(uA + dO1, sH1, szB);
            cpa16(uA + 8192 + dO0, sL0, szA);
            cpa16(uA + 8192 + dO1, sL1, szB);
            #pragma unroll
            for (int q = 0; q < 4; q++)
                cpa16(uStage + stDstBase + q * 16, uSrc + q * 4, 16);
            CPA_COMMIT();

            const int NCH = I_DIM / 64;  // 8
            for (int ch = 0; ch < NCH; ch++) {
                CPA_WAIT0();
                __syncthreads();   // make ALL threads' cp.async data visible before stage reads
                {
                    const float* stgW = (const float*)(dsm + 65536 + (ch & 1) * 16384);
                    #pragma unroll
                    for (int it = 0; it < 4; it++) {
                        uint32_t h01, l01, h23, l23;
                        bsplit2(bw[it][0], bw[it][1], h01, l01);
                        bsplit2(bw[it][2], bw[it][3], h23, l23);
                        uint32_t o = SWZB((uint32_t)(pn * 128 + (pkb + it * 4) * 8));
                        *(uint2*)(dsm + 32768 + o) = make_uint2(h01, h23);
                        *(uint2*)(dsm + 49152 + o) = make_uint2(l01, l23);
                        int kb4 = (pkb + it * 4) * 4;
                        float c0 = stgW[(kb4 + 0) * 64 + pn];
                        float c1 = stgW[(kb4 + 1) * 64 + pn];
                        float c2 = stgW[(kb4 + 2) * 64 + pn];
                        float c3 = stgW[(kb4 + 3) * 64 + pn];
                        bsplit2(c0, c1, h01, l01);
                        bsplit2(c2, c3, h23, l23);
                        uint32_t o2 = SWZB((uint32_t)((64 + pn) * 128 + (pkb + it * 4) * 8));
                        *(uint2*)(dsm + 32768 + o2) = make_uint2(h01, h23);
                        *(uint2*)(dsm + 49152 + o2) = make_uint2(l01, l23);
                    }
                }
                __syncthreads();

                if (ch + 1 < NCH) {
                    uint32_t ab = uA + (uint32_t)(((ch + 1) & 1) * 16384);
                    uint32_t boff = (uint32_t)((ch + 1) * 128);
                    cpa16(ab + dO0, sH0 + boff, szA);
                    cpa16(ab + dO1, sH1 + boff, szB);
                    cpa16(ab + 8192 + dO0, sL0 + boff, szA);
                    cpa16(ab + 8192 + dO1, sL1 + boff, szB);
                    uint32_t sb = uStage + (uint32_t)(((ch + 1) & 1) * 16384);
                    const float* us = uSrc + (size_t)(ch + 1) * 64 * H_DIM;
                    #pragma unroll
                    for (int q = 0; q < 4; q++)
                        cpa16(sb + stDstBase + q * 16, us + q * 4, 16);
                    CPA_COMMIT();
                    int k0n = (ch + 1) * 64;
                    #pragma unroll
                    for (int it = 0; it < 4; it++) {
                        const float* p = wdB + (size_t)(k0n + (pkb + it * 4) * 4) * H_DIM + pn;
                        bw[it][0] = p[0]; bw[it][1] = p[H_DIM];
                        bw[it][2] = p[2 * H_DIM]; bw[it][3] = p[3 * H_DIM];
                    }
                }

                uint32_t uAhi = uA + (uint32_t)((ch & 1) * 16384);
                uint32_t uAlo = uAhi + 8192;
                #pragma unroll
                for (int ks = 0; ks < 4; ks++) {
                    uint32_t ah[2][4], al[2][4];
                    #pragma unroll
                    for (int mf = 0; mf < 2; mf++) {
                        uint32_t o = SWZB((uint32_t)((aRow + mf * 16) * 128) + (uint32_t)(ks * 32) + aKb);
                        ldm4(ah[mf], uAhi + o);
                        ldm4(al[mf], uAlo + o);
                    }
                    uint32_t ob1 = SWZB((uint32_t)(bRow * 128) + (uint32_t)(ks * 32) + bKb);
                    uint32_t ob2 = SWZB((uint32_t)((bRow + 16) * 128) + (uint32_t)(ks * 32) + bKb);
                    uint32_t bh[8], bl[8];
                    ldm4(bh, uBh + ob1);
                    ldm4(bh + 4, uBh + ob2);
                    ldm4(bl, uBl + ob1);
                    ldm4(bl + 4, uBl + ob2);
                    #pragma unroll
                    for (int mf = 0; mf < 2; mf++) {
                        #pragma unroll
                        for (int nf = 0; nf < 4; nf++) {
                            mma16816(acc[mf][nf], ah[mf], bh[nf * 2], bh[nf * 2 + 1]);
                            mma16816(acc[mf][nf], ah[mf], bl[nf * 2], bl[nf * 2 + 1]);
                            mma16816(acc[mf][nf], al[mf], bh[nf * 2], bh[nf * 2 + 1]);
                        }
                    }
                }
                __syncthreads();
            }

            #pragma unroll
            for (int mf = 0; mf < 2; mf++) {
                #pragma unroll
                for (int nf = 0; nf < 4; nf++) {
                    int col = nt * 128 + wn * 32 + nf * 8 + lc;
                    #pragma unroll
                    for (int half = 0; half < 2; half++) {
                        int row = wm * 32 + mf * 16 + lr + half * 8;
                        if (m0 + row < ne) {
                            int rid = s_rids[row];
                            float wt = s_wts[row];
                            float2 o;
                            o.x = wt * acc[mf][nf][half * 2 + 0];
                            o.y = wt * acc[mf][nf][half * 2 + 1];
                            *(float2*)(g_ybuf + (size_t)rid * H_DIM + col) = o;
                        }
                    }
                }
            }
        }
    }
}

// ---------------- kernel: deterministic combine (float4 vectorized) ----------------
__global__ __launch_bounds__(256) void combine_kernel(float* __restrict__ out)
{
    int idx = blockIdx.x * 256 + threadIdx.x;   // T*H/4 = 65536 threads
    int t  = idx >> 8;                          // H/4 = 256 float4 per row
    int h4 = idx & 255;
    const float4* base = (const float4*)g_ybuf + (size_t)t * TOPK * (H_DIM / 4) + h4;
    float4 s = base[0];
    #pragma unroll
    for (int k = 1; k < TOPK; k++) {
        float4 v = base[(size_t)k * (H_DIM / 4)];
        s.x += v.x; s.y += v.y; s.z += v.z; s.w += v.w;
    }
    ((float4*)out)[idx] = s;
}

// ---------------- launch ----------------
#define GEMM_SMEM (32768 + 32768 + 32768)   // 96KB
#define N_PERSIST 296

extern "C" void kernel_launch(void* const* d_in, const int* in_sizes, int n_in,
                              void* d_out, int out_size)
{
    const float* x      = (const float*)d_in[0];
    const float* gate_w = (const float*)d_in[1];
    const float* bias   = (const float*)d_in[2];
    const float* Wg     = (const float*)d_in[3];
    const float* Wu     = (const float*)d_in[4];
    const float* Wd     = (const float*)d_in[5];
    float* out = (float*)d_out;

    cudaFuncSetAttribute(moe_gemm_kernel, cudaFuncAttributeMaxDynamicSharedMemorySize, GEMM_SMEM);

    routing_kernel<<<T_TOK, 128>>>(x, gate_w, bias);
    build_lists_kernel<<<1, 1024>>>();
    moe_gemm_kernel<<<N_PERSIST, 256, GEMM_SMEM>>>(Wg, Wu, Wd);
    combine_kernel<<<(T_TOK * H_DIM / 4) / 256, 256>>>(out);
}

// round 14
// speedup vs baseline: 1.2332x; 1.1047x over previous
#include <cuda_runtime.h>
#include <cuda_bf16.h>
#include <cuda_fp16.h>
#include <math.h>
#include <stdint.h>

#define T_TOK 256
#define H_DIM 1024
#define I_DIM 512
#define E_EXP 32
#define TOPK  8
#define NGRP  8
#define GSZ   4
#define TKG   4

#define SWZB(o) ((o) ^ (((o) >> 3) & 0x70))

// ---------------- helpers ----------------
__device__ __forceinline__ uint32_t smem_u32(const void* p) {
    uint32_t a;
    asm("{ .reg .u64 t; cvta.to.shared.u64 t, %1; cvt.u32.u64 %0, t; }" : "=r"(a) : "l"(p));
    return a;
}

// pack 2 fp32 -> fp16x2 (e0 in low half, e1 in high half), round-to-nearest
__device__ __forceinline__ uint32_t cvt2h(float e0, float e1) {
    uint32_t h;
    asm("cvt.rn.f16x2.f32 %0, %1, %2;" : "=r"(h) : "f"(e1), "f"(e0));
    return h;
}

// split 2 fp32 -> packed fp16x2 hi + fp16x2 lo (lo = exact residual, rn)
__device__ __forceinline__ void fsplit2(float e0, float e1, uint32_t &h, uint32_t &l) {
    asm("cvt.rn.f16x2.f32 %0, %1, %2;" : "=r"(h) : "f"(e1), "f"(e0));
    float f0, f1;
    asm("{ .reg .f16 a, b;\n\t mov.b32 {a, b}, %2;\n\t cvt.f32.f16 %0, a;\n\t cvt.f32.f16 %1, b; }"
        : "=f"(f0), "=f"(f1) : "r"(h));
    float r0 = e0 - f0, r1 = e1 - f1;
    asm("cvt.rn.f16x2.f32 %0, %1, %2;" : "=r"(l) : "f"(r1), "f"(r0));
}

__device__ __forceinline__ void ldm4(uint32_t r[4], uint32_t addr) {
    asm volatile("ldmatrix.sync.aligned.m8n8.x4.shared.b16 {%0,%1,%2,%3}, [%4];"
        : "=r"(r[0]), "=r"(r[1]), "=r"(r[2]), "=r"(r[3]) : "r"(addr));
}

__device__ __forceinline__ void mma16816(float d[4], const uint32_t a[4],
                                         uint32_t b0, uint32_t b1) {
    asm volatile("mma.sync.aligned.m16n8k16.row.col.f32.f16.f16.f32 "
        "{%0,%1,%2,%3}, {%4,%5,%6,%7}, {%8,%9}, {%0,%1,%2,%3};"
        : "+f"(d[0]), "+f"(d[1]), "+f"(d[2]), "+f"(d[3])
        : "r"(a[0]), "r"(a[1]), "r"(a[2]), "r"(a[3]), "r"(b0), "r"(b1));
}

__device__ __forceinline__ void cpa16(uint32_t dst, const void* src, uint32_t sz) {
    asm volatile("cp.async.cg.shared.global [%0], [%1], 16, %2;"
        :: "r"(dst), "l"(src), "r"(sz) : "memory");
}
#define CPA_COMMIT() asm volatile("cp.async.commit_group;" ::: "memory")
#define CPA_WAIT0()  asm volatile("cp.async.wait_group 0;" ::: "memory")

// ---------------- device scratch ----------------
__device__ int   g_topk_idx[T_TOK * TOPK];
__device__ float g_topk_w[T_TOK * TOPK];
__device__ int   g_cnt[E_EXP];
__device__ int   g_tok[E_EXP * T_TOK];
__device__ int   g_slot[E_EXP * T_TOK];
__device__ float g_wt[E_EXP * T_TOK];
__device__ uint16_t g_xhi[T_TOK * H_DIM];    // fp16 hi of x
__device__ uint16_t g_xlo[T_TOK * H_DIM];    // fp16 lo of x
__device__ uint16_t g_ahi[T_TOK * TOPK * I_DIM];
__device__ uint16_t g_alo[T_TOK * TOPK * I_DIM];
__device__ float g_ybuf[T_TOK * TOPK * H_DIM];

// work queue
__device__ int g_pairs[E_EXP * 4];   // (e<<2)|mt
__device__ int g_npair;
__device__ int g_ctr;
__device__ int g_rdy[E_EXP * 4];     // per-pair gateup completion count (target 8)

// ---------------- kernel 1: routing (coalesced GEMV + fused x split) ----------------
__global__ __launch_bounds__(128) void routing_kernel(
    const float* __restrict__ x, const float* __restrict__ gate_w,
    const float* __restrict__ bias)
{
    int t = blockIdx.x;
    __shared__ float xs[H_DIM];
    __shared__ float part[4][E_EXP];
    __shared__ float sc[E_EXP];
    __shared__ float sfc[E_EXP];
    int tid = threadIdx.x;
    for (int i = tid; i < H_DIM / 4; i += 128) {
        float4 v = *(const float4*)(x + (size_t)t * H_DIM + i * 4);
        *(float4*)&xs[i * 4] = v;
        uint32_t h0, l0, h1, l1;
        fsplit2(v.x, v.y, h0, l0);
        fsplit2(v.z, v.w, h1, l1);
        ((uint2*)(g_xhi + (size_t)t * H_DIM))[i] = make_uint2(h0, h1);
        ((uint2*)(g_xlo + (size_t)t * H_DIM))[i] = make_uint2(l0, l1);
    }
    __syncthreads();
    int warp = tid >> 5, lane = tid & 31;
    {
        float s = 0.f;
        const float* gw = gate_w + lane;
        int h0 = warp * (H_DIM / 4);
        #pragma unroll 4
        for (int h = h0; h < h0 + H_DIM / 4; h++)
            s += xs[h] * gw[(size_t)h * E_EXP];
        part[warp][lane] = s;
    }
    __syncthreads();
    if (tid < E_EXP) {
        float s = part[0][tid] + part[1][tid] + part[2][tid] + part[3][tid];
        float sig = 1.f / (1.f + expf(-s));
        sc[tid] = sig;
        sfc[tid] = sig + bias[tid];
    }
    __syncthreads();
    if (tid == 0) {
        float gs[NGRP];
        #pragma unroll
        for (int g = 0; g < NGRP; g++) {
            float m1 = -1e30f, m2 = -1e30f;
            #pragma unroll
            for (int j = 0; j < GSZ; j++) {
                float v = sfc[g * GSZ + j];
                if (v > m1) { m2 = m1; m1 = v; }
                else if (v > m2) { m2 = v; }
            }
            gs[g] = m1 + m2;
        }
        bool gsel[NGRP];
        #pragma unroll
        for (int g = 0; g < NGRP; g++) gsel[g] = false;
        for (int r = 0; r < TKG; r++) {
            int b = -1;
            for (int g = 0; g < NGRP; g++)
                if (!gsel[g] && (b < 0 || gs[g] > gs[b])) b = g;
            gsel[b] = true;
        }
        float masked[E_EXP];
        bool used[E_EXP];
        #pragma unroll
        for (int e = 0; e < E_EXP; e++) {
            masked[e] = gsel[e >> 2] ? sfc[e] : 0.0f;
            used[e] = false;
        }
        int idx[TOPK];
        float wsum = 0.f;
        for (int r = 0; r < TOPK; r++) {
            int b = -1;
            for (int e = 0; e < E_EXP; e++)
                if (!used[e] && (b < 0 || masked[e] > masked[b])) b = e;
            used[b] = true;
            idx[r] = b;
            wsum += sc[b];
        }
        float scale = 2.5f / (wsum + 1e-20f);
        for (int r = 0; r < TOPK; r++) {
            g_topk_idx[t * TOPK + r] = idx[r];
            g_topk_w[t * TOPK + r]   = sc[idx[r]] * scale;
        }
    }
}

// ---------------- kernel 2: compaction + work-queue setup ----------------
__global__ __launch_bounds__(1024) void build_lists_kernel()
{
    int e = threadIdx.x >> 5;
    int lane = threadIdx.x & 31;
    int cnt = 0;
    for (int t0 = 0; t0 < T_TOK; t0 += 32) {
        int t = t0 + lane;
        int found = -1;
        #pragma unroll
        for (int k = 0; k < TOPK; k++)
            if (g_topk_idx[t * TOPK + k] == e) found = k;
        unsigned m = __ballot_sync(0xffffffffu, found >= 0);
        if (found >= 0) {
            int pos = cnt + __popc(m & ((1u << lane) - 1));
            g_tok [e * T_TOK + pos] = t;
            g_slot[e * T_TOK + pos] = found;
            g_wt  [e * T_TOK + pos] = g_topk_w[t * TOPK + found];
        }
        cnt += __popc(m);
    }
    if (lane == 0) g_cnt[e] = cnt;
    if (threadIdx.x < E_EXP * 4) g_rdy[threadIdx.x] = 0;
    __syncthreads();
    if (threadIdx.x == 0) {
        int n = 0;
        for (int ee = 0; ee < E_EXP; ee++) {
            int c = g_cnt[ee];
            for (int mt = 0; mt * 64 < c; mt++) g_pairs[n++] = (ee << 2) | mt;
        }
        g_npair = n;
        g_ctr = 0;
    }
}

// ---------------- fused persistent GEMM kernel (fp16 2-term) ----------------
// smem (80KB): A [0,32K): {A0h,A0l,A1h,A1l}@8K; B fp16 single [32K,48K);
// W fp32 stage double [48K,80K): {S0 16K, S1 16K}

__global__ __launch_bounds__(256, 2) void moe_gemm_kernel(
    const float* __restrict__ Wg,
    const float* __restrict__ Wu,
    const float* __restrict__ Wd)
{
    extern __shared__ __align__(128) char dsm[];
    __shared__ int   s_widx;
    __shared__ int   s_toks[64];
    __shared__ int   s_rids[64];
    __shared__ float s_wts[64];

    int tid = threadIdx.x;
    int lane = tid & 31;
    int w = tid >> 5;
    int wm = w & 1;
    int wn = w >> 1;   // 0..3

    uint32_t uA = smem_u32(dsm);
    uint32_t uBh = uA + 32768;
    uint32_t uStage = uA + 49152;

    int arow0 = tid >> 3, aseg = tid & 7;
    int arow1 = arow0 + 32;
    uint32_t dO0 = SWZB((uint32_t)(arow0 * 128 + aseg * 16));
    uint32_t dO1 = SWZB((uint32_t)(arow1 * 128 + aseg * 16));

    // weight staging addressing
    int srow = tid >> 2;            // 0..63 (k-row within chunk)
    int sq4  = (tid & 3) * 16;      // float offset of 64B group within 64-float row
    uint32_t stDstBase = (uint32_t)(srow * 256 + (tid & 3) * 64);

    int aRow = wm * 32 + (lane & 15);
    uint32_t aKb = (uint32_t)((lane >> 4) * 16);
    int bRow = wn * 32 + (lane & 7) + ((lane >> 4) << 3);
    uint32_t bKb = (uint32_t)(((lane >> 3) & 1) * 16);

    int pkb = tid >> 6, pn = tid & 63;
    int lr = lane >> 2, lc = (lane & 3) * 2;

    for (;;) {
        __syncthreads();
        if (tid == 0) s_widx = atomicAdd(&g_ctr, 1);
        __syncthreads();
        int widx = s_widx;
        int npair = g_npair;
        if (widx >= npair * 16) return;

        if (widx < npair * 8) {
            // ================= GATEUP TILE =================
            int pidx = widx >> 3;
            int nt = widx & 7;
            int pr = g_pairs[pidx];
            int e = pr >> 2, mt = pr & 3;
            int ne = g_cnt[e];
            int m0 = mt * 64;

            if (tid < 64) {
                int i = m0 + tid;
                if (i < ne) {
                    int tk = g_tok[e * T_TOK + i];
                    s_toks[tid] = tk;
                    s_rids[tid] = tk * TOPK + g_slot[e * T_TOK + i];
                } else { s_toks[tid] = -1; s_rids[tid] = -1; }
            }
            __syncthreads();

            int tokA = s_toks[arow0], tokB = s_toks[arow1];
            const char* sH0 = (const char*)g_xhi + ((size_t)(tokA < 0 ? 0 : tokA) * H_DIM) * 2 + aseg * 16;
            const char* sH1 = (const char*)g_xhi + ((size_t)(tokB < 0 ? 0 : tokB) * H_DIM) * 2 + aseg * 16;
            const char* sL0 = (const char*)g_xlo + ((size_t)(tokA < 0 ? 0 : tokA) * H_DIM) * 2 + aseg * 16;
            const char* sL1 = (const char*)g_xlo + ((size_t)(tokB < 0 ? 0 : tokB) * H_DIM) * 2 + aseg * 16;
            uint32_t szA = (tokA >= 0) ? 16u : 0u;
            uint32_t szB = (tokB >= 0) ? 16u : 0u;

            float acc[2][4][4];
            #pragma unroll
            for (int a = 0; a < 2; a++)
                #pragma unroll
                for (int b = 0; b < 4; b++)
                    #pragma unroll
                    for (int c = 0; c < 4; c++) acc[a][b][c] = 0.f;

            const float* wgB = Wg + (size_t)e * H_DIM * I_DIM + nt * 64;
            const float* wuB = Wu + (size_t)e * H_DIM * I_DIM + nt * 64;
            const float* uSrc = wuB + (size_t)srow * I_DIM + sq4;

            float bw[4][4];
            #pragma unroll
            for (int it = 0; it < 4; it++) {
                const float* p = wgB + (size_t)((pkb + it * 4) * 4) * I_DIM + pn;
                bw[it][0] = p[0]; bw[it][1] = p[I_DIM];
                bw[it][2] = p[2 * I_DIM]; bw[it][3] = p[3 * I_DIM];
            }
            cpa16(uA + dO0, sH0, szA);
            cpa16(uA + dO1, sH1, szB);
            cpa16(uA + 8192 + dO0, sL0, szA);
            cpa16(uA + 8192 + dO1, sL1, szB);
            #pragma unroll
            for (int q = 0; q < 4; q++)
                cpa16(uStage + stDstBase + q * 16, uSrc + q * 4, 16);
            CPA_COMMIT();

            const int NCH = H_DIM / 64;  // 16
            for (int ch = 0; ch < NCH; ch++) {
                CPA_WAIT0();
                __syncthreads();   // make ALL threads' cp.async data visible
                // store phase: g-half from bw regs, u-half from fp32 stage (fp16 hi only)
                {
                    const float* stgW = (const float*)(dsm + 49152 + (ch & 1) * 16384);
                    #pragma unroll
                    for (int it = 0; it < 4; it++) {
                        uint32_t h01 = cvt2h(bw[it][0], bw[it][1]);
                        uint32_t h23 = cvt2h(bw[it][2], bw[it][3]);
                        uint32_t o = SWZB((uint32_t)(pn * 128 + (pkb + it * 4) * 8));
                        *(uint2*)(dsm + 32768 + o) = make_uint2(h01, h23);
                        int kb4 = (pkb + it * 4) * 4;
                        float c0 = stgW[(kb4 + 0) * 64 + pn];
                        float c1 = stgW[(kb4 + 1) * 64 + pn];
                        float c2 = stgW[(kb4 + 2) * 64 + pn];
                        float c3 = stgW[(kb4 + 3) * 64 + pn];
                        uint32_t u01 = cvt2h(c0, c1);
                        uint32_t u23 = cvt2h(c2, c3);
                        uint32_t o2 = SWZB((uint32_t)((64 + pn) * 128 + (pkb + it * 4) * 8));
                        *(uint2*)(dsm + 32768 + o2) = make_uint2(u01, u23);
                    }
                }
                __syncthreads();

                if (ch + 1 < NCH) {
                    uint32_t ab = uA + (uint32_t)(((ch + 1) & 1) * 16384);
                    uint32_t boff = (uint32_t)((ch + 1) * 128);
                    cpa16(ab + dO0, sH0 + boff, szA);
                    cpa16(ab + dO1, sH1 + boff, szB);
                    cpa16(ab + 8192 + dO0, sL0 + boff, szA);
                    cpa16(ab + 8192 + dO1, sL1 + boff, szB);
                    uint32_t sb = uStage + (uint32_t)(((ch + 1) & 1) * 16384);
                    const float* us = uSrc + (size_t)(ch + 1) * 64 * I_DIM;
                    #pragma unroll
                    for (int q = 0; q < 4; q++)
                        cpa16(sb + stDstBase + q * 16, us + q * 4, 16);
                    CPA_COMMIT();
                    int k0n = (ch + 1) * 64;
                    #pragma unroll
                    for (int it = 0; it < 4; it++) {
                        const float* p = wgB + (size_t)(k0n + (pkb + it * 4) * 4) * I_DIM + pn;
                        bw[it][0] = p[0]; bw[it][1] = p[I_DIM];
                        bw[it][2] = p[2 * I_DIM]; bw[it][3] = p[3 * I_DIM];
                    }
                }

                uint32_t uAhi = uA + (uint32_t)((ch & 1) * 16384);
                uint32_t uAlo = uAhi + 8192;
                #pragma unroll
                for (int ks = 0; ks < 4; ks++) {
                    uint32_t ah[2][4], al[2][4];
                    #pragma unroll
                    for (int mf = 0; mf < 2; mf++) {
                        uint32_t o = SWZB((uint32_t)((aRow + mf * 16) * 128) + (uint32_t)(ks * 32) + aKb);
                        ldm4(ah[mf], uAhi + o);
                        ldm4(al[mf], uAlo + o);
                    }
                    uint32_t ob1 = SWZB((uint32_t)(bRow * 128) + (uint32_t)(ks * 32) + bKb);
                    uint32_t ob2 = SWZB((uint32_t)((bRow + 16) * 128) + (uint32_t)(ks * 32) + bKb);
                    uint32_t bh[8];
                    ldm4(bh, uBh + ob1);
                    ldm4(bh + 4, uBh + ob2);
                    #pragma unroll
                    for (int mf = 0; mf < 2; mf++) {
                        #pragma unroll
                        for (int nf = 0; nf < 4; nf++) {
                            mma16816(acc[mf][nf], ah[mf], bh[nf * 2], bh[nf * 2 + 1]);
                            mma16816(acc[mf][nf], al[mf], bh[nf * 2], bh[nf * 2 + 1]);
                        }
                    }
                }
                __syncthreads();   // protect single B buffer before next store
            }

            // epilogue: stage accs to smem, a = silu(g)*u, write fp16 hi/lo
            float* stg = (float*)dsm;
            #pragma unroll
            for (int mf = 0; mf < 2; mf++) {
                #pragma unroll
                for (int nf = 0; nf < 4; nf++) {
                    int col = wn * 32 + nf * 8 + lc;
                    #pragma unroll
                    for (int half = 0; half < 2; half++) {
                        int row = wm * 32 + mf * 16 + lr + half * 8;
                        *(float2*)&stg[row * 128 + col] =
                            make_float2(acc[mf][nf][half * 2], acc[mf][nf][half * 2 + 1]);
                    }
                }
            }
            __syncthreads();
            #pragma unroll
            for (int p = 0; p < 8; p++) {
                int idx2 = tid + p * 256;
                int row = idx2 >> 5;
                int cp = idx2 & 31;
                int rid = s_rids[row];
                if (rid >= 0) {
                    float2 g = *(float2*)&stg[row * 128 + cp * 2];
                    float2 u = *(float2*)&stg[row * 128 + 64 + cp * 2];
                    float a0 = (g.x / (1.f + expf(-g.x))) * u.x;
                    float a1 = (g.y / (1.f + expf(-g.y))) * u.y;
                    uint32_t h, l;
                    fsplit2(a0, a1, h, l);
                    size_t off = (size_t)rid * I_DIM + nt * 64 + cp * 2;
                    *(uint32_t*)(g_ahi + off) = h;
                    *(uint32_t*)(g_alo + off) = l;
                }
            }
            __threadfence();
            __syncthreads();
            if (tid == 0) atomicAdd(&g_rdy[pidx], 1);
        } else {
            // ================= DOWN TILE =================
            int w2 = widx - npair * 8;
            int pidx = w2 >> 3;
            int nt = w2 & 7;
            int pr = g_pairs[pidx];
            int e = pr >> 2, mt = pr & 3;
            int ne = g_cnt[e];
            int m0 = mt * 64;

            if (tid == 0) {
                while (atomicAdd(&g_rdy[pidx], 0) < 8) { }
            }
            __syncthreads();

            if (tid < 64) {
                int i = m0 + tid;
                if (i < ne) {
                    int tk = g_tok[e * T_TOK + i];
                    s_rids[tid] = tk * TOPK + g_slot[e * T_TOK + i];
                    s_wts[tid]  = g_wt[e * T_TOK + i];
                } else { s_rids[tid] = -1; s_wts[tid] = 0.f; }
            }
            __syncthreads();

            int ridA = s_rids[arow0], ridB = s_rids[arow1];
            const char* sH0 = (const char*)g_ahi + ((size_t)(ridA < 0 ? 0 : ridA) * I_DIM) * 2 + aseg * 16;
            const char* sH1 = (const char*)g_ahi + ((size_t)(ridB < 0 ? 0 : ridB) * I_DIM) * 2 + aseg * 16;
            const char* sL0 = (const char*)g_alo + ((size_t)(ridA < 0 ? 0 : ridA) * I_DIM) * 2 + aseg * 16;
            const char* sL1 = (const char*)g_alo + ((size_t)(ridB < 0 ? 0 : ridB) * I_DIM) * 2 + aseg * 16;
            uint32_t szA = (ridA >= 0) ? 16u : 0u;
            uint32_t szB = (ridB >= 0) ? 16u : 0u;

            float acc[2][4][4];
            #pragma unroll
            for (int a = 0; a < 2; a++)
                #pragma unroll
                for (int b = 0; b < 4; b++)
                    #pragma unroll
                    for (int c = 0; c < 4; c++) acc[a][b][c] = 0.f;

            const float* wdB = Wd + (size_t)e * I_DIM * H_DIM + nt * 128;
            const float* uSrc = wdB + 64 + (size_t)srow * H_DIM + sq4;
            float bw[4][4];
            #pragma unroll
            for (int it = 0; it < 4; it++) {
                const float* p = wdB + (size_t)((pkb + it * 4) * 4) * H_DIM + pn;
                bw[it][0] = p[0]; bw[it][1] = p[H_DIM];
                bw[it][2] = p[2 * H_DIM]; bw[it][3] = p[3 * H_DIM];
            }
            cpa16(uA + dO0, sH0, szA);
            cpa16(uA + dO1, sH1, szB);
            cpa16(uA + 8192 + dO0, sL0, szA);
            cpa16(uA + 8192 + dO1, sL1, szB);
            #pragma unroll
            for (int q = 0; q < 4; q++)
                cpa16(uStage + stDstBase + q * 16, uSrc + q * 4, 16);
            CPA_COMMIT();

            const int NCH = I_DIM / 64;  // 8
            for (int ch = 0; ch < NCH; ch++) {
                CPA_WAIT0();
                __syncthreads();
                {
                    const float* stgW = (const float*)(dsm + 49152 + (ch & 1) * 16384);
                    #pragma unroll
                    for (int it = 0; it < 4; it++) {
                        uint32_t h01 = cvt2h(bw[it][0], bw[it][1]);
                        uint32_t h23 = cvt2h(bw[it][2], bw[it][3]);
                        uint32_t o = SWZB((uint32_t)(pn * 128 + (pkb + it * 4) * 8));
                        *(uint2*)(dsm + 32768 + o) = make_uint2(h01, h23);
                        int kb4 = (pkb + it * 4) * 4;
                        float c0 = stgW[(kb4 + 0) * 64 + pn];
                        float c1 = stgW[(kb4 + 1) * 64 + pn];
                        float c2 = stgW[(kb4 + 2) * 64 + pn];
                        float c3 = stgW[(kb4 + 3) * 64 + pn];
                        uint32_t u01 = cvt2h(c0, c1);
                        uint32_t u23 = cvt2h(c2, c3);
                        uint32_t o2 = SWZB((uint32_t)((64 + pn) * 128 + (pkb + it * 4) * 8));
                        *(uint2*)(dsm + 32768 + o2) = make_uint2(u01, u23);
                    }
                }
                __syncthreads();

                if (ch + 1 < NCH) {
                    uint32_t ab = uA + (uint32_t)(((ch + 1) & 1) * 16384);
                    uint32_t boff = (uint32_t)((ch + 1) * 128);
                    cpa16(ab + dO0, sH0 + boff, szA);
                    cpa16(ab + dO1, sH1 + boff, szB);
                    cpa16(ab + 8192 + dO0, sL0 + boff, szA);
                    cpa16(ab + 8192 + dO1, sL1 + boff, szB);
                    uint32_t sb = uStage + (uint32_t)(((ch + 1) & 1) * 16384);
                    const float* us = uSrc + (size_t)(ch + 1) * 64 * H_DIM;
                    #pragma unroll
                    for (int q = 0; q < 4; q++)
                        cpa16(sb + stDstBase + q * 16, us + q * 4, 16);
                    CPA_COMMIT();
                    int k0n = (ch + 1) * 64;
                    #pragma unroll
                    for (int it = 0; it < 4; it++) {
                        const float* p = wdB + (size_t)(k0n + (pkb + it * 4) * 4) * H_DIM + pn;
                        bw[it][0] = p[0]; bw[it][1] = p[H_DIM];
                        bw[it][2] = p[2 * H_DIM]; bw[it][3] = p[3 * H_DIM];
                    }
                }

                uint32_t uAhi = uA + (uint32_t)((ch & 1) * 16384);
                uint32_t uAlo = uAhi + 8192;
                #pragma unroll
                for (int ks = 0; ks < 4; ks++) {
                    uint32_t ah[2][4], al[2][4];
                    #pragma unroll
                    for (int mf = 0; mf < 2; mf++) {
                        uint32_t o = SWZB((uint32_t)((aRow + mf * 16) * 128) + (uint32_t)(ks * 32) + aKb);
                        ldm4(ah[mf], uAhi + o);
                        ldm4(al[mf], uAlo + o);
                    }
                    uint32_t ob1 = SWZB((uint32_t)(bRow * 128) + (uint32_t)(ks * 32) + bKb);
                    uint32_t ob2 = SWZB((uint32_t)((bRow + 16) * 128) + (uint32_t)(ks * 32) + bKb);
                    uint32_t bh[8];
                    ldm4(bh, uBh + ob1);
                    ldm4(bh + 4, uBh + ob2);
                    #pragma unroll
                    for (int mf = 0; mf < 2; mf++) {
                        #pragma unroll
                        for (int nf = 0; nf < 4; nf++) {
                            mma16816(acc[mf][nf], ah[mf], bh[nf * 2], bh[nf * 2 + 1]);
                            mma16816(acc[mf][nf], al[mf], bh[nf * 2], bh[nf * 2 + 1]);
                        }
                    }
                }
                __syncthreads();
            }

            #pragma unroll
            for (int mf = 0; mf < 2; mf++) {
                #pragma unroll
                for (int nf = 0; nf < 4; nf++) {
                    int col = nt * 128 + wn * 32 + nf * 8 + lc;
                    #pragma unroll
                    for (int half = 0; half < 2; half++) {
                        int row = wm * 32 + mf * 16 + lr + half * 8;
                        if (m0 + row < ne) {
                            int rid = s_rids[row];
                            float wt = s_wts[row];
                            float2 o;
                            o.x = wt * acc[mf][nf][half * 2 + 0];
                            o.y = wt * acc[mf][nf][half * 2 + 1];
                            *(float2*)(g_ybuf + (size_t)rid * H_DIM + col) = o;
                        }
                    }
                }
            }
        }
    }
}

// ---------------- kernel: deterministic combine (scalar, R10 version) ----------------
__global__ __launch_bounds__(256) void combine_kernel(float* __restrict__ out)
{
    int idx = blockIdx.x * 256 + threadIdx.x;
    int t = idx >> 10;
    int h = idx & 1023;
    float s = 0.f;
    #pragma unroll
    for (int k = 0; k < TOPK; k++)
        s += g_ybuf[((size_t)t * TOPK + k) * H_DIM + h];
    out[idx] = s;
}

// ---------------- launch ----------------
#define GEMM_SMEM (32768 + 16384 + 32768)   // 80KB
#define N_PERSIST 296

extern "C" void kernel_launch(void* const* d_in, const int* in_sizes, int n_in,
                              void* d_out, int out_size)
{
    const float* x      = (const float*)d_in[0];
    const float* gate_w = (const float*)d_in[1];
    const float* bias   = (const float*)d_in[2];
    const float* Wg     = (const float*)d_in[3];
    const float* Wu     = (const float*)d_in[4];
    const float* Wd     = (const float*)d_in[5];
    float* out = (float*)d_out;

    cudaFuncSetAttribute(moe_gemm_kernel, cudaFuncAttributeMaxDynamicSharedMemorySize, GEMM_SMEM);

    routing_kernel<<<T_TOK, 128>>>(x, gate_w, bias);
    build_lists_kernel<<<1, 1024>>>();
    moe_gemm_kernel<<<N_PERSIST, 256, GEMM_SMEM>>>(Wg, Wu, Wd);
    combine_kernel<<<(T_TOK * H_DIM) / 256, 256>>>(out);
}

// round 15
// speedup vs baseline: 1.2683x; 1.0284x over previous
#include <cuda_runtime.h>
#include <cuda_bf16.h>
#include <cuda_fp16.h>
#include <math.h>
#include <stdint.h>

#define T_TOK 256
#define H_DIM 1024
#define I_DIM 512
#define E_EXP 32
#define TOPK  8
#define NGRP  8
#define GSZ   4
#define TKG   4

#define SWZB(o) ((o) ^ (((o) >> 3) & 0x70))

// ---------------- helpers ----------------
__device__ __forceinline__ uint32_t smem_u32(const void* p) {
    uint32_t a;
    asm("{ .reg .u64 t; cvta.to.shared.u64 t, %1; cvt.u32.u64 %0, t; }" : "=r"(a) : "l"(p));
    return a;
}

// pack 2 fp32 -> fp16x2 (e0 low half, e1 high half), rn
__device__ __forceinline__ uint32_t cvt2h(float e0, float e1) {
    uint32_t h;
    asm("cvt.rn.f16x2.f32 %0, %1, %2;" : "=r"(h) : "f"(e1), "f"(e0));
    return h;
}

// split 2 fp32 -> packed fp16x2 hi + fp16x2 lo (lo = exact residual)
__device__ __forceinline__ void fsplit2(float e0, float e1, uint32_t &h, uint32_t &l) {
    asm("cvt.rn.f16x2.f32 %0, %1, %2;" : "=r"(h) : "f"(e1), "f"(e0));
    float f0, f1;
    asm("{ .reg .f16 a, b;\n\t mov.b32 {a, b}, %2;\n\t cvt.f32.f16 %0, a;\n\t cvt.f32.f16 %1, b; }"
        : "=f"(f0), "=f"(f1) : "r"(h));
    float r0 = e0 - f0, r1 = e1 - f1;
    asm("cvt.rn.f16x2.f32 %0, %1, %2;" : "=r"(l) : "f"(r1), "f"(r0));
}

__device__ __forceinline__ void ldm4(uint32_t r[4], uint32_t addr) {
    asm volatile("ldmatrix.sync.aligned.m8n8.x4.shared.b16 {%0,%1,%2,%3}, [%4];"
        : "=r"(r[0]), "=r"(r[1]), "=r"(r[2]), "=r"(r[3]) : "r"(addr));
}

__device__ __forceinline__ void mma16816(float d[4], const uint32_t a[4],
                                         uint32_t b0, uint32_t b1) {
    asm volatile("mma.sync.aligned.m16n8k16.row.col.f32.f16.f16.f32 "
        "{%0,%1,%2,%3}, {%4,%5,%6,%7}, {%8,%9}, {%0,%1,%2,%3};"
        : "+f"(d[0]), "+f"(d[1]), "+f"(d[2]), "+f"(d[3])
        : "r"(a[0]), "r"(a[1]), "r"(a[2]), "r"(a[3]), "r"(b0), "r"(b1));
}

__device__ __forceinline__ void cpa16(uint32_t dst, const void* src, uint32_t sz) {
    asm volatile("cp.async.cg.shared.global [%0], [%1], 16, %2;"
        :: "r"(dst), "l"(src), "r"(sz) : "memory");
}
#define CPA_COMMIT() asm volatile("cp.async.commit_group;" ::: "memory")
#define CPA_WAIT0()  asm volatile("cp.async.wait_group 0;" ::: "memory")

// ---------------- device scratch ----------------
__device__ int   g_topk_idx[T_TOK * TOPK];
__device__ float g_topk_w[T_TOK * TOPK];
__device__ int   g_cnt[E_EXP];
__device__ int   g_tok[E_EXP * T_TOK];
__device__ int   g_slot[E_EXP * T_TOK];
__device__ float g_wt[E_EXP * T_TOK];
__device__ uint16_t g_xhi[T_TOK * H_DIM];    // fp16 hi of x
__device__ uint16_t g_xlo[T_TOK * H_DIM];    // fp16 lo of x
__device__ uint16_t g_ahi[T_TOK * TOPK * I_DIM];   // fp16(a) only (no lo)
__device__ float g_ybuf[T_TOK * TOPK * H_DIM];

// work queue
__device__ int g_pairs[E_EXP * 4];
__device__ int g_npair;
__device__ int g_ctr;
__device__ int g_rdy[E_EXP * 4];

// ---------------- kernel 1: routing (coalesced GEMV + fused x split) ----------------
__global__ __launch_bounds__(128) void routing_kernel(
    const float* __restrict__ x, const float* __restrict__ gate_w,
    const float* __restrict__ bias)
{
    int t = blockIdx.x;
    __shared__ float xs[H_DIM];
    __shared__ float part[4][E_EXP];
    __shared__ float sc[E_EXP];
    __shared__ float sfc[E_EXP];
    int tid = threadIdx.x;
    for (int i = tid; i < H_DIM / 4; i += 128) {
        float4 v = *(const float4*)(x + (size_t)t * H_DIM + i * 4);
        *(float4*)&xs[i * 4] = v;
        uint32_t h0, l0, h1, l1;
        fsplit2(v.x, v.y, h0, l0);
        fsplit2(v.z, v.w, h1, l1);
        ((uint2*)(g_xhi + (size_t)t * H_DIM))[i] = make_uint2(h0, h1);
        ((uint2*)(g_xlo + (size_t)t * H_DIM))[i] = make_uint2(l0, l1);
    }
    __syncthreads();
    int warp = tid >> 5, lane = tid & 31;
    {
        float s = 0.f;
        const float* gw = gate_w + lane;
        int h0 = warp * (H_DIM / 4);
        #pragma unroll 4
        for (int h = h0; h < h0 + H_DIM / 4; h++)
            s += xs[h] * gw[(size_t)h * E_EXP];
        part[warp][lane] = s;
    }
    __syncthreads();
    if (tid < E_EXP) {
        float s = part[0][tid] + part[1][tid] + part[2][tid] + part[3][tid];
        float sig = 1.f / (1.f + expf(-s));
        sc[tid] = sig;
        sfc[tid] = sig + bias[tid];
    }
    __syncthreads();
    if (tid == 0) {
        float gs[NGRP];
        #pragma unroll
        for (int g = 0; g < NGRP; g++) {
            float m1 = -1e30f, m2 = -1e30f;
            #pragma unroll
            for (int j = 0; j < GSZ; j++) {
                float v = sfc[g * GSZ + j];
                if (v > m1) { m2 = m1; m1 = v; }
                else if (v > m2) { m2 = v; }
            }
            gs[g] = m1 + m2;
        }
        bool gsel[NGRP];
        #pragma unroll
        for (int g = 0; g < NGRP; g++) gsel[g] = false;
        for (int r = 0; r < TKG; r++) {
            int b = -1;
            for (int g = 0; g < NGRP; g++)
                if (!gsel[g] && (b < 0 || gs[g] > gs[b])) b = g;
            gsel[b] = true;
        }
        float masked[E_EXP];
        bool used[E_EXP];
        #pragma unroll
        for (int e = 0; e < E_EXP; e++) {
            masked[e] = gsel[e >> 2] ? sfc[e] : 0.0f;
            used[e] = false;
        }
        int idx[TOPK];
        float wsum = 0.f;
        for (int r = 0; r < TOPK; r++) {
            int b = -1;
            for (int e = 0; e < E_EXP; e++)
                if (!used[e] && (b < 0 || masked[e] > masked[b])) b = e;
            used[b] = true;
            idx[r] = b;
            wsum += sc[b];
        }
        float scale = 2.5f / (wsum + 1e-20f);
        for (int r = 0; r < TOPK; r++) {
            g_topk_idx[t * TOPK + r] = idx[r];
            g_topk_w[t * TOPK + r]   = sc[idx[r]] * scale;
        }
    }
}

// ---------------- kernel 2: compaction + work-queue setup ----------------
__global__ __launch_bounds__(1024) void build_lists_kernel()
{
    int e = threadIdx.x >> 5;
    int lane = threadIdx.x & 31;
    int cnt = 0;
    for (int t0 = 0; t0 < T_TOK; t0 += 32) {
        int t = t0 + lane;
        int found = -1;
        #pragma unroll
        for (int k = 0; k < TOPK; k++)
            if (g_topk_idx[t * TOPK + k] == e) found = k;
        unsigned m = __ballot_sync(0xffffffffu, found >= 0);
        if (found >= 0) {
            int pos = cnt + __popc(m & ((1u << lane) - 1));
            g_tok [e * T_TOK + pos] = t;
            g_slot[e * T_TOK + pos] = found;
            g_wt  [e * T_TOK + pos] = g_topk_w[t * TOPK + found];
        }
        cnt += __popc(m);
    }
    if (lane == 0) g_cnt[e] = cnt;
    if (threadIdx.x < E_EXP * 4) g_rdy[threadIdx.x] = 0;
    __syncthreads();
    if (threadIdx.x == 0) {
        int n = 0;
        for (int ee = 0; ee < E_EXP; ee++) {
            int c = g_cnt[ee];
            for (int mt = 0; mt * 64 < c; mt++) g_pairs[n++] = (ee << 2) | mt;
        }
        g_npair = n;
        g_ctr = 0;
    }
}

// ---------------- fused persistent GEMM kernel (fp16; gateup 2-term, down 1-term) ----------------
// smem (96KB): A [0,32K): {A0h,A0l,A1h,A1l}@8K; B fp16 DOUBLE [32K,64K): buf0 16K, buf1 16K;
// W fp32 stage double [64K,96K): {S0 16K, S1 16K}.  2 syncs per chunk.

__global__ __launch_bounds__(256, 2) void moe_gemm_kernel(
    const float* __restrict__ Wg,
    const float* __restrict__ Wu,
    const float* __restrict__ Wd)
{
    extern __shared__ __align__(128) char dsm[];
    __shared__ int   s_widx;
    __shared__ int   s_toks[64];
    __shared__ int   s_rids[64];
    __shared__ float s_wts[64];

    int tid = threadIdx.x;
    int lane = tid & 31;
    int w = tid >> 5;
    int wm = w & 1;
    int wn = w >> 1;

    uint32_t uA = smem_u32(dsm);
    uint32_t uB = uA + 32768;
    uint32_t uStage = uA + 65536;

    int arow0 = tid >> 3, aseg = tid & 7;
    int arow1 = arow0 + 32;
    uint32_t dO0 = SWZB((uint32_t)(arow0 * 128 + aseg * 16));
    uint32_t dO1 = SWZB((uint32_t)(arow1 * 128 + aseg * 16));

    int srow = tid >> 2;
    int sq4  = (tid & 3) * 16;
    uint32_t stDstBase = (uint32_t)(srow * 256 + (tid & 3) * 64);

    int aRow = wm * 32 + (lane & 15);
    uint32_t aKb = (uint32_t)((lane >> 4) * 16);
    int bRow = wn * 32 + (lane & 7) + ((lane >> 4) << 3);
    uint32_t bKb = (uint32_t)(((lane >> 3) & 1) * 16);

    int pkb = tid >> 6, pn = tid & 63;
    int lr = lane >> 2, lc = (lane & 3) * 2;

    for (;;) {
        __syncthreads();
        if (tid == 0) s_widx = atomicAdd(&g_ctr, 1);
        __syncthreads();
        int widx = s_widx;
        int npair = g_npair;
        if (widx >= npair * 16) return;

        if (widx < npair * 8) {
            // ================= GATEUP TILE (2-term A) =================
            int pidx = widx >> 3;
            int nt = widx & 7;
            int pr = g_pairs[pidx];
            int e = pr >> 2, mt = pr & 3;
            int ne = g_cnt[e];
            int m0 = mt * 64;

            if (tid < 64) {
                int i = m0 + tid;
                if (i < ne) {
                    int tk = g_tok[e * T_TOK + i];
                    s_toks[tid] = tk;
                    s_rids[tid] = tk * TOPK + g_slot[e * T_TOK + i];
                } else { s_toks[tid] = -1; s_rids[tid] = -1; }
            }
            __syncthreads();

            int tokA = s_toks[arow0], tokB = s_toks[arow1];
            const char* sH0 = (const char*)g_xhi + ((size_t)(tokA < 0 ? 0 : tokA) * H_DIM) * 2 + aseg * 16;
            const char* sH1 = (const char*)g_xhi + ((size_t)(tokB < 0 ? 0 : tokB) * H_DIM) * 2 + aseg * 16;
            const char* sL0 = (const char*)g_xlo + ((size_t)(tokA < 0 ? 0 : tokA) * H_DIM) * 2 + aseg * 16;
            const char* sL1 = (const char*)g_xlo + ((size_t)(tokB < 0 ? 0 : tokB) * H_DIM) * 2 + aseg * 16;
            uint32_t szA = (tokA >= 0) ? 16u : 0u;
            uint32_t szB = (tokB >= 0) ? 16u : 0u;

            float acc[2][4][4];
            #pragma unroll
            for (int a = 0; a < 2; a++)
                #pragma unroll
                for (int b = 0; b < 4; b++)
                    #pragma unroll
                    for (int c = 0; c < 4; c++) acc[a][b][c] = 0.f;

            const float* wgB = Wg + (size_t)e * H_DIM * I_DIM + nt * 64;
            const float* wuB = Wu + (size_t)e * H_DIM * I_DIM + nt * 64;
            const float* uSrc = wuB + (size_t)srow * I_DIM + sq4;

            float bw[4][4];
            #pragma unroll
            for (int it = 0; it < 4; it++) {
                const float* p = wgB + (size_t)((pkb + it * 4) * 4) * I_DIM + pn;
                bw[it][0] = p[0]; bw[it][1] = p[I_DIM];
                bw[it][2] = p[2 * I_DIM]; bw[it][3] = p[3 * I_DIM];
            }
            cpa16(uA + dO0, sH0, szA);
            cpa16(uA + dO1, sH1, szB);
            cpa16(uA + 8192 + dO0, sL0, szA);
            cpa16(uA + 8192 + dO1, sL1, szB);
            #pragma unroll
            for (int q = 0; q < 4; q++)
                cpa16(uStage + stDstBase + q * 16, uSrc + q * 4, 16);
            CPA_COMMIT();

            const int NCH = H_DIM / 64;  // 16
            for (int ch = 0; ch < NCH; ch++) {
                CPA_WAIT0();
                __syncthreads();   // cp.async visibility (all threads), MMA(ch-1) complete
                // convert: B[ch&1] <- g half (regs) + u half (stage LDS)
                {
                    char* BH = dsm + 32768 + (ch & 1) * 16384;
                    const float* stgW = (const float*)(dsm + 65536 + (ch & 1) * 16384);
                    #pragma unroll
                    for (int it = 0; it < 4; it++) {
                        uint32_t h01 = cvt2h(bw[it][0], bw[it][1]);
                        uint32_t h23 = cvt2h(bw[it][2], bw[it][3]);
                        uint32_t o = SWZB((uint32_t)(pn * 128 + (pkb + it * 4) * 8));
                        *(uint2*)(BH + o) = make_uint2(h01, h23);
                        int kb4 = (pkb + it * 4) * 4;
                        float c0 = stgW[(kb4 + 0) * 64 + pn];
                        float c1 = stgW[(kb4 + 1) * 64 + pn];
                        float c2 = stgW[(kb4 + 2) * 64 + pn];
                        float c3 = stgW[(kb4 + 3) * 64 + pn];
                        uint32_t u01 = cvt2h(c0, c1);
                        uint32_t u23 = cvt2h(c2, c3);
                        uint32_t o2 = SWZB((uint32_t)((64 + pn) * 128 + (pkb + it * 4) * 8));
                        *(uint2*)(BH + o2) = make_uint2(u01, u23);
                    }
                }
                __syncthreads();   // B[ch&1] ready

                if (ch + 1 < NCH) {
                    uint32_t ab = uA + (uint32_t)(((ch + 1) & 1) * 16384);
                    uint32_t boff = (uint32_t)((ch + 1) * 128);
                    cpa16(ab + dO0, sH0 + boff, szA);
                    cpa16(ab + dO1, sH1 + boff, szB);
                    cpa16(ab + 8192 + dO0, sL0 + boff, szA);
                    cpa16(ab + 8192 + dO1, sL1 + boff, szB);
                    uint32_t sb = uStage + (uint32_t)(((ch + 1) & 1) * 16384);
                    const float* us = uSrc + (size_t)(ch + 1) * 64 * I_DIM;
                    #pragma unroll
                    for (int q = 0; q < 4; q++)
                        cpa16(sb + stDstBase + q * 16, us + q * 4, 16);
                    CPA_COMMIT();
                    int k0n = (ch + 1) * 64;
                    #pragma unroll
                    for (int it = 0; it < 4; it++) {
                        const float* p = wgB + (size_t)(k0n + (pkb + it * 4) * 4) * I_DIM + pn;
                        bw[it][0] = p[0]; bw[it][1] = p[I_DIM];
                        bw[it][2] = p[2 * I_DIM]; bw[it][3] = p[3 * I_DIM];
                    }
                }

                uint32_t uAhi = uA + (uint32_t)((ch & 1) * 16384);
                uint32_t uAlo = uAhi + 8192;
                uint32_t uBh = uB + (uint32_t)((ch & 1) * 16384);
                #pragma unroll
                for (int ks = 0; ks < 4; ks++) {
                    uint32_t ah[2][4], al[2][4];
                    #pragma unroll
                    for (int mf = 0; mf < 2; mf++) {
                        uint32_t o = SWZB((uint32_t)((aRow + mf * 16) * 128) + (uint32_t)(ks * 32) + aKb);
                        ldm4(ah[mf], uAhi + o);
                        ldm4(al[mf], uAlo + o);
                    }
                    uint32_t ob1 = SWZB((uint32_t)(bRow * 128) + (uint32_t)(ks * 32) + bKb);
                    uint32_t ob2 = SWZB((uint32_t)((bRow + 16) * 128) + (uint32_t)(ks * 32) + bKb);
                    uint32_t bh[8];
                    ldm4(bh, uBh + ob1);
                    ldm4(bh + 4, uBh + ob2);
                    #pragma unroll
                    for (int mf = 0; mf < 2; mf++) {
                        #pragma unroll
                        for (int nf = 0; nf < 4; nf++) {
                            mma16816(acc[mf][nf], ah[mf], bh[nf * 2], bh[nf * 2 + 1]);
                            mma16816(acc[mf][nf], al[mf], bh[nf * 2], bh[nf * 2 + 1]);
                        }
                    }
                }
                // no trailing sync: B/A/stage all double-buffered
            }

            // epilogue: stage accs to smem (A region), a = silu(g)*u, write fp16 hi only
            __syncthreads();   // all MMA reads of A region done
            float* stg = (float*)dsm;
            #pragma unroll
            for (int mf = 0; mf < 2; mf++) {
                #pragma unroll
                for (int nf = 0; nf < 4; nf++) {
                    int col = wn * 32 + nf * 8 + lc;
                    #pragma unroll
                    for (int half = 0; half < 2; half++) {
                        int row = wm * 32 + mf * 16 + lr + half * 8;
                        *(float2*)&stg[row * 128 + col] =
                            make_float2(acc[mf][nf][half * 2], acc[mf][nf][half * 2 + 1]);
                    }
                }
            }
            __syncthreads();
            #pragma unroll
            for (int p = 0; p < 8; p++) {
                int idx2 = tid + p * 256;
                int row = idx2 >> 5;
                int cp = idx2 & 31;
                int rid = s_rids[row];
                if (rid >= 0) {
                    float2 g = *(float2*)&stg[row * 128 + cp * 2];
                    float2 u = *(float2*)&stg[row * 128 + 64 + cp * 2];
                    float a0 = (g.x / (1.f + expf(-g.x))) * u.x;
                    float a1 = (g.y / (1.f + expf(-g.y))) * u.y;
                    size_t off = (size_t)rid * I_DIM + nt * 64 + cp * 2;
                    *(uint32_t*)(g_ahi + off) = cvt2h(a0, a1);
                }
            }
            __threadfence();
            __syncthreads();
            if (tid == 0) atomicAdd(&g_rdy[pidx], 1);
        } else {
            // ================= DOWN TILE (1-term A) =================
            int w2 = widx - npair * 8;
            int pidx = w2 >> 3;
            int nt = w2 & 7;
            int pr = g_pairs[pidx];
            int e = pr >> 2, mt = pr & 3;
            int ne = g_cnt[e];
            int m0 = mt * 64;

            if (tid == 0) {
                while (atomicAdd(&g_rdy[pidx], 0) < 8) { }
            }
            __syncthreads();

            if (tid < 64) {
                int i = m0 + tid;
                if (i < ne) {
                    int tk = g_tok[e * T_TOK + i];
                    s_rids[tid] = tk * TOPK + g_slot[e * T_TOK + i];
                    s_wts[tid]  = g_wt[e * T_TOK + i];
                } else { s_rids[tid] = -1; s_wts[tid] = 0.f; }
            }
            __syncthreads();

            int ridA = s_rids[arow0], ridB = s_rids[arow1];
            const char* sH0 = (const char*)g_ahi + ((size_t)(ridA < 0 ? 0 : ridA) * I_DIM) * 2 + aseg * 16;
            const char* sH1 = (const char*)g_ahi + ((size_t)(ridB < 0 ? 0 : ridB) * I_DIM) * 2 + aseg * 16;
            uint32_t szA = (ridA >= 0) ? 16u : 0u;
            uint32_t szB = (ridB >= 0) ? 16u : 0u;

            float acc[2][4][4];
            #pragma unroll
            for (int a = 0; a < 2; a++)
                #pragma unroll
                for (int b = 0; b < 4; b++)
                    #pragma unroll
                    for (int c = 0; c < 4; c++) acc[a][b][c] = 0.f;

            const float* wdB = Wd + (size_t)e * I_DIM * H_DIM + nt * 128;
            const float* uSrc = wdB + 64 + (size_t)srow * H_DIM + sq4;
            float bw[4][4];
            #pragma unroll
            for (int it = 0; it < 4; it++) {
                const float* p = wdB + (size_t)((pkb + it * 4) * 4) * H_DIM + pn;
                bw[it][0] = p[0]; bw[it][1] = p[H_DIM];
                bw[it][2] = p[2 * H_DIM]; bw[it][3] = p[3 * H_DIM];
            }
            cpa16(uA + dO0, sH0, szA);
            cpa16(uA + dO1, sH1, szB);
            #pragma unroll
            for (int q = 0; q < 4; q++)
                cpa16(uStage + stDstBase + q * 16, uSrc + q * 4, 16);
            CPA_COMMIT();

            const int NCH = I_DIM / 64;  // 8
            for (int ch = 0; ch < NCH; ch++) {
                CPA_WAIT0();
                __syncthreads();
                {
                    char* BH = dsm + 32768 + (ch & 1) * 16384;
                    const float* stgW = (const float*)(dsm + 65536 + (ch & 1) * 16384);
                    #pragma unroll
                    for (int it = 0; it < 4; it++) {
                        uint32_t h01 = cvt2h(bw[it][0], bw[it][1]);
                        uint32_t h23 = cvt2h(bw[it][2], bw[it][3]);
                        uint32_t o = SWZB((uint32_t)(pn * 128 + (pkb + it * 4) * 8));
                        *(uint2*)(BH + o) = make_uint2(h01, h23);
                        int kb4 = (pkb + it * 4) * 4;
                        float c0 = stgW[(kb4 + 0) * 64 + pn];
                        float c1 = stgW[(kb4 + 1) * 64 + pn];
                        float c2 = stgW[(kb4 + 2) * 64 + pn];
                        float c3 = stgW[(kb4 + 3) * 64 + pn];
                        uint32_t u01 = cvt2h(c0, c1);
                        uint32_t u23 = cvt2h(c2, c3);
                        uint32_t o2 = SWZB((uint32_t)((64 + pn) * 128 + (pkb + it * 4) * 8));
                        *(uint2*)(BH + o2) = make_uint2(u01, u23);
                    }
                }
                __syncthreads();

                if (ch + 1 < NCH) {
                    uint32_t ab = uA + (uint32_t)(((ch + 1) & 1) * 16384);
                    uint32_t boff = (uint32_t)((ch + 1) * 128);
                    cpa16(ab + dO0, sH0 + boff, szA);
                    cpa16(ab + dO1, sH1 + boff, szB);
                    uint32_t sb = uStage + (uint32_t)(((ch + 1) & 1) * 16384);
                    const float* us = uSrc + (size_t)(ch + 1) * 64 * H_DIM;
                    #pragma unroll
                    for (int q = 0; q < 4; q++)
                        cpa16(sb + stDstBase + q * 16, us + q * 4, 16);
                    CPA_COMMIT();
                    int k0n = (ch + 1) * 64;
                    #pragma unroll
                    for (int it = 0; it < 4; it++) {
                        const float* p = wdB + (size_t)(k0n + (pkb + it * 4) * 4) * H_DIM + pn;
                        bw[it][0] = p[0]; bw[it][1] = p[H_DIM];
                        bw[it][2] = p[2 * H_DIM]; bw[it][3] = p[3 * H_DIM];
                    }
                }

                uint32_t uAhi = uA + (uint32_t)((ch & 1) * 16384);
                uint32_t uBh = uB + (uint32_t)((ch & 1) * 16384);
                #pragma unroll
                for (int ks = 0; ks < 4; ks++) {
                    uint32_t ah[2][4];
                    #pragma unroll
                    for (int mf = 0; mf < 2; mf++) {
                        uint32_t o = SWZB((uint32_t)((aRow + mf * 16) * 128) + (uint32_t)(ks * 32) + aKb);
                        ldm4(ah[mf], uAhi + o);
                    }
                    uint32_t ob1 = SWZB((uint32_t)(bRow * 128) + (uint32_t)(ks * 32) + bKb);
                    uint32_t ob2 = SWZB((uint32_t)((bRow + 16) * 128) + (uint32_t)(ks * 32) + bKb);
                    uint32_t bh[8];
                    ldm4(bh, uBh + ob1);
                    ldm4(bh + 4, uBh + ob2);
                    #pragma unroll
                    for (int mf = 0; mf < 2; mf++) {
                        #pragma unroll
                        for (int nf = 0; nf < 4; nf++) {
                            mma16816(acc[mf][nf], ah[mf], bh[nf * 2], bh[nf * 2 + 1]);
                        }
                    }
                }
            }

            #pragma unroll
            for (int mf = 0; mf < 2; mf++) {
                #pragma unroll
                for (int nf = 0; nf < 4; nf++) {
                    int col = nt * 128 + wn * 32 + nf * 8 + lc;
                    #pragma unroll
                    for (int half = 0; half < 2; half++) {
                        int row = wm * 32 + mf * 16 + lr + half * 8;
                        if (m0 + row < ne) {
                            int rid = s_rids[row];
                            float wt = s_wts[row];
                            float2 o;
                            o.x = wt * acc[mf][nf][half * 2 + 0];
                            o.y = wt * acc[mf][nf][half * 2 + 1];
                            *(float2*)(g_ybuf + (size_t)rid * H_DIM + col) = o;
                        }
                    }
                }
            }
        }
    }
}

// ---------------- kernel: deterministic combine ----------------
__global__ __launch_bounds__(256) void combine_kernel(float* __restrict__ out)
{
    int idx = blockIdx.x * 256 + threadIdx.x;
    int t = idx >> 10;
    int h = idx & 1023;
    float s = 0.f;
    #pragma unroll
    for (int k = 0; k < TOPK; k++)
        s += g_ybuf[((size_t)t * TOPK + k) * H_DIM + h];
    out[idx] = s;
}

// ---------------- launch ----------------
#define GEMM_SMEM (32768 + 32768 + 32768)   // 96KB
#define N_PERSIST 296

extern "C" void kernel_launch(void* const* d_in, const int* in_sizes, int n_in,
                              void* d_out, int out_size)
{
    const float* x      = (const float*)d_in[0];
    const float* gate_w = (const float*)d_in[1];
    const float* bias   = (const float*)d_in[2];
    const float* Wg     = (const float*)d_in[3];
    const float* Wu     = (const float*)d_in[4];
    const float* Wd     = (const float*)d_in[5];
    float* out = (float*)d_out;

    cudaFuncSetAttribute(moe_gemm_kernel, cudaFuncAttributeMaxDynamicSharedMemorySize, GEMM_SMEM);

    routing_kernel<<<T_TOK, 128>>>(x, gate_w, bias);
    build_lists_kernel<<<1, 1024>>>();
    moe_gemm_kernel<<<N_PERSIST, 256, GEMM_SMEM>>>(Wg, Wu, Wd);
    combine_kernel<<<(T_TOK * H_DIM) / 256, 256>>>(out);
}

// round 16
// speedup vs baseline: 1.2880x; 1.0156x over previous
#include <cuda_runtime.h>
#include <cuda_bf16.h>
#include <cuda_fp16.h>
#include <math.h>
#include <stdint.h>

#define T_TOK 256
#define H_DIM 1024
#define I_DIM 512
#define E_EXP 32
#define TOPK  8
#define NGRP  8
#define GSZ   4
#define TKG   4

#define SWZB(o) ((o) ^ (((o) >> 3) & 0x70))

// ---------------- helpers ----------------
__device__ __forceinline__ uint32_t smem_u32(const void* p) {
    uint32_t a;
    asm("{ .reg .u64 t; cvta.to.shared.u64 t, %1; cvt.u32.u64 %0, t; }" : "=r"(a) : "l"(p));
    return a;
}

// pack 2 fp32 -> fp16x2 (e0 low half, e1 high half), rn
__device__ __forceinline__ uint32_t cvt2h(float e0, float e1) {
    uint32_t h;
    asm("cvt.rn.f16x2.f32 %0, %1, %2;" : "=r"(h) : "f"(e1), "f"(e0));
    return h;
}

__device__ __forceinline__ void ldm4(uint32_t r[4], uint32_t addr) {
    asm volatile("ldmatrix.sync.aligned.m8n8.x4.shared.b16 {%0,%1,%2,%3}, [%4];"
        : "=r"(r[0]), "=r"(r[1]), "=r"(r[2]), "=r"(r[3]) : "r"(addr));
}

__device__ __forceinline__ void mma16816(float d[4], const uint32_t a[4],
                                         uint32_t b0, uint32_t b1) {
    asm volatile("mma.sync.aligned.m16n8k16.row.col.f32.f16.f16.f32 "
        "{%0,%1,%2,%3}, {%4,%5,%6,%7}, {%8,%9}, {%0,%1,%2,%3};"
        : "+f"(d[0]), "+f"(d[1]), "+f"(d[2]), "+f"(d[3])
        : "r"(a[0]), "r"(a[1]), "r"(a[2]), "r"(a[3]), "r"(b0), "r"(b1));
}

__device__ __forceinline__ void cpa16(uint32_t dst, const void* src, uint32_t sz) {
    asm volatile("cp.async.cg.shared.global [%0], [%1], 16, %2;"
        :: "r"(dst), "l"(src), "r"(sz) : "memory");
}
#define CPA_COMMIT() asm volatile("cp.async.commit_group;" ::: "memory")
#define CPA_WAIT0()  asm volatile("cp.async.wait_group 0;" ::: "memory")

// ---------------- device scratch ----------------
__device__ int   g_topk_idx[T_TOK * TOPK];
__device__ float g_topk_w[T_TOK * TOPK];
__device__ int   g_cnt[E_EXP];
__device__ int   g_tok[E_EXP * T_TOK];
__device__ int   g_slot[E_EXP * T_TOK];
__device__ float g_wt[E_EXP * T_TOK];
__device__ uint16_t g_xhi[T_TOK * H_DIM];          // fp16(x)
__device__ uint16_t g_ahi[T_TOK * TOPK * I_DIM];   // fp16(a)
__device__ float g_ybuf[T_TOK * TOPK * H_DIM];

// work queue
__device__ int g_pairs[E_EXP * 4];
__device__ int g_npair;
__device__ int g_ctr;
__device__ int g_rdy[E_EXP * 4];

// ---------------- kernel 1: routing (coalesced GEMV + fused x->fp16) ----------------
__global__ __launch_bounds__(128) void routing_kernel(
    const float* __restrict__ x, const float* __restrict__ gate_w,
    const float* __restrict__ bias)
{
    int t = blockIdx.x;
    __shared__ float xs[H_DIM];
    __shared__ float part[4][E_EXP];
    __shared__ float sc[E_EXP];
    __shared__ float sfc[E_EXP];
    int tid = threadIdx.x;
    for (int i = tid; i < H_DIM / 4; i += 128) {
        float4 v = *(const float4*)(x + (size_t)t * H_DIM + i * 4);
        *(float4*)&xs[i * 4] = v;
        uint32_t h0 = cvt2h(v.x, v.y);
        uint32_t h1 = cvt2h(v.z, v.w);
        ((uint2*)(g_xhi + (size_t)t * H_DIM))[i] = make_uint2(h0, h1);
    }
    __syncthreads();
    int warp = tid >> 5, lane = tid & 31;
    {
        float s = 0.f;
        const float* gw = gate_w + lane;
        int h0 = warp * (H_DIM / 4);
        #pragma unroll 4
        for (int h = h0; h < h0 + H_DIM / 4; h++)
            s += xs[h] * gw[(size_t)h * E_EXP];
        part[warp][lane] = s;
    }
    __syncthreads();
    if (tid < E_EXP) {
        float s = part[0][tid] + part[1][tid] + part[2][tid] + part[3][tid];
        float sig = 1.f / (1.f + expf(-s));
        sc[tid] = sig;
        sfc[tid] = sig + bias[tid];
    }
    __syncthreads();
    if (tid == 0) {
        float gs[NGRP];
        #pragma unroll
        for (int g = 0; g < NGRP; g++) {
            float m1 = -1e30f, m2 = -1e30f;
            #pragma unroll
            for (int j = 0; j < GSZ; j++) {
                float v = sfc[g * GSZ + j];
                if (v > m1) { m2 = m1; m1 = v; }
                else if (v > m2) { m2 = v; }
            }
            gs[g] = m1 + m2;
        }
        bool gsel[NGRP];
        #pragma unroll
        for (int g = 0; g < NGRP; g++) gsel[g] = false;
        for (int r = 0; r < TKG; r++) {
            int b = -1;
            for (int g = 0; g < NGRP; g++)
                if (!gsel[g] && (b < 0 || gs[g] > gs[b])) b = g;
            gsel[b] = true;
        }
        float masked[E_EXP];
        bool used[E_EXP];
        #pragma unroll
        for (int e = 0; e < E_EXP; e++) {
            masked[e] = gsel[e >> 2] ? sfc[e] : 0.0f;
            used[e] = false;
        }
        int idx[TOPK];
        float wsum = 0.f;
        for (int r = 0; r < TOPK; r++) {
            int b = -1;
            for (int e = 0; e < E_EXP; e++)
                if (!used[e] && (b < 0 || masked[e] > masked[b])) b = e;
            used[b] = true;
            idx[r] = b;
            wsum += sc[b];
        }
        float scale = 2.5f / (wsum + 1e-20f);
        for (int r = 0; r < TOPK; r++) {
            g_topk_idx[t * TOPK + r] = idx[r];
            g_topk_w[t * TOPK + r]   = sc[idx[r]] * scale;
        }
    }
}

// ---------------- kernel 2: compaction + work-queue setup ----------------
__global__ __launch_bounds__(1024) void build_lists_kernel()
{
    int e = threadIdx.x >> 5;
    int lane = threadIdx.x & 31;
    int cnt = 0;
    for (int t0 = 0; t0 < T_TOK; t0 += 32) {
        int t = t0 + lane;
        int found = -1;
        #pragma unroll
        for (int k = 0; k < TOPK; k++)
            if (g_topk_idx[t * TOPK + k] == e) found = k;
        unsigned m = __ballot_sync(0xffffffffu, found >= 0);
        if (found >= 0) {
            int pos = cnt + __popc(m & ((1u << lane) - 1));
            g_tok [e * T_TOK + pos] = t;
            g_slot[e * T_TOK + pos] = found;
            g_wt  [e * T_TOK + pos] = g_topk_w[t * TOPK + found];
        }
        cnt += __popc(m);
    }
    if (lane == 0) g_cnt[e] = cnt;
    if (threadIdx.x < E_EXP * 4) g_rdy[threadIdx.x] = 0;
    __syncthreads();
    if (threadIdx.x == 0) {
        int n = 0;
        for (int ee = 0; ee < E_EXP; ee++) {
            int c = g_cnt[ee];
            for (int mt = 0; mt * 64 < c; mt++) g_pairs[n++] = (ee << 2) | mt;
        }
        g_npair = n;
        g_ctr = 0;
    }
}

// ---------------- fused persistent GEMM kernel (fp16 1-term both GEMMs) ----------------
// smem (96KB): A [0,32K): buf0 8K, buf1 8K (hi only; rest unused);
// B fp16 DOUBLE [32K,64K): buf0 16K, buf1 16K; W fp32 stage double [64K,96K).
// 2 syncs per chunk.

__global__ __launch_bounds__(256, 2) void moe_gemm_kernel(
    const float* __restrict__ Wg,
    const float* __restrict__ Wu,
    const float* __restrict__ Wd)
{
    extern __shared__ __align__(128) char dsm[];
    __shared__ int   s_widx;
    __shared__ int   s_toks[64];
    __shared__ int   s_rids[64];
    __shared__ float s_wts[64];

    int tid = threadIdx.x;
    int lane = tid & 31;
    int w = tid >> 5;
    int wm = w & 1;
    int wn = w >> 1;

    uint32_t uA = smem_u32(dsm);
    uint32_t uB = uA + 32768;
    uint32_t uStage = uA + 65536;

    int arow0 = tid >> 3, aseg = tid & 7;
    int arow1 = arow0 + 32;
    uint32_t dO0 = SWZB((uint32_t)(arow0 * 128 + aseg * 16));
    uint32_t dO1 = SWZB((uint32_t)(arow1 * 128 + aseg * 16));

    int srow = tid >> 2;
    int sq4  = (tid & 3) * 16;
    uint32_t stDstBase = (uint32_t)(srow * 256 + (tid & 3) * 64);

    int aRow = wm * 32 + (lane & 15);
    uint32_t aKb = (uint32_t)((lane >> 4) * 16);
    int bRow = wn * 32 + (lane & 7) + ((lane >> 4) << 3);
    uint32_t bKb = (uint32_t)(((lane >> 3) & 1) * 16);

    int pkb = tid >> 6, pn = tid & 63;
    int lr = lane >> 2, lc = (lane & 3) * 2;

    for (;;) {
        __syncthreads();
        if (tid == 0) s_widx = atomicAdd(&g_ctr, 1);
        __syncthreads();
        int widx = s_widx;
        int npair = g_npair;
        if (widx >= npair * 16) return;

        if (widx < npair * 8) {
            // ================= GATEUP TILE (1-term A) =================
            int pidx = widx >> 3;
            int nt = widx & 7;
            int pr = g_pairs[pidx];
            int e = pr >> 2, mt = pr & 3;
            int ne = g_cnt[e];
            int m0 = mt * 64;

            if (tid < 64) {
                int i = m0 + tid;
                if (i < ne) {
                    int tk = g_tok[e * T_TOK + i];
                    s_toks[tid] = tk;
                    s_rids[tid] = tk * TOPK + g_slot[e * T_TOK + i];
                } else { s_toks[tid] = -1; s_rids[tid] = -1; }
            }
            __syncthreads();

            int tokA = s_toks[arow0], tokB = s_toks[arow1];
            const char* sH0 = (const char*)g_xhi + ((size_t)(tokA < 0 ? 0 : tokA) * H_DIM) * 2 + aseg * 16;
            const char* sH1 = (const char*)g_xhi + ((size_t)(tokB < 0 ? 0 : tokB) * H_DIM) * 2 + aseg * 16;
            uint32_t szA = (tokA >= 0) ? 16u : 0u;
            uint32_t szB = (tokB >= 0) ? 16u : 0u;

            float acc[2][4][4];
            #pragma unroll
            for (int a = 0; a < 2; a++)
                #pragma unroll
                for (int b = 0; b < 4; b++)
                    #pragma unroll
                    for (int c = 0; c < 4; c++) acc[a][b][c] = 0.f;

            const float* wgB = Wg + (size_t)e * H_DIM * I_DIM + nt * 64;
            const float* wuB = Wu + (size_t)e * H_DIM * I_DIM + nt * 64;
            const float* uSrc = wuB + (size_t)srow * I_DIM + sq4;

            float bw[4][4];
            #pragma unroll
            for (int it = 0; it < 4; it++) {
                const float* p = wgB + (size_t)((pkb + it * 4) * 4) * I_DIM + pn;
                bw[it][0] = p[0]; bw[it][1] = p[I_DIM];
                bw[it][2] = p[2 * I_DIM]; bw[it][3] = p[3 * I_DIM];
            }
            cpa16(uA + dO0, sH0, szA);
            cpa16(uA + dO1, sH1, szB);
            #pragma unroll
            for (int q = 0; q < 4; q++)
                cpa16(uStage + stDstBase + q * 16, uSrc + q * 4, 16);
            CPA_COMMIT();

            const int NCH = H_DIM / 64;  // 16
            for (int ch = 0; ch < NCH; ch++) {
                CPA_WAIT0();
                __syncthreads();   // cp.async visibility, MMA(ch-1) complete
                {
                    char* BH = dsm + 32768 + (ch & 1) * 16384;
                    const float* stgW = (const float*)(dsm + 65536 + (ch & 1) * 16384);
                    #pragma unroll
                    for (int it = 0; it < 4; it++) {
                        uint32_t h01 = cvt2h(bw[it][0], bw[it][1]);
                        uint32_t h23 = cvt2h(bw[it][2], bw[it][3]);
                        uint32_t o = SWZB((uint32_t)(pn * 128 + (pkb + it * 4) * 8));
                        *(uint2*)(BH + o) = make_uint2(h01, h23);
                        int kb4 = (pkb + it * 4) * 4;
                        float c0 = stgW[(kb4 + 0) * 64 + pn];
                        float c1 = stgW[(kb4 + 1) * 64 + pn];
                        float c2 = stgW[(kb4 + 2) * 64 + pn];
                        float c3 = stgW[(kb4 + 3) * 64 + pn];
                        uint32_t u01 = cvt2h(c0, c1);
                        uint32_t u23 = cvt2h(c2, c3);
                        uint32_t o2 = SWZB((uint32_t)((64 + pn) * 128 + (pkb + it * 4) * 8));
                        *(uint2*)(BH + o2) = make_uint2(u01, u23);
                    }
                }
                __syncthreads();   // B[ch&1] ready

                if (ch + 1 < NCH) {
                    uint32_t ab = uA + (uint32_t)(((ch + 1) & 1) * 8192);
                    uint32_t boff = (uint32_t)((ch + 1) * 128);
                    cpa16(ab + dO0, sH0 + boff, szA);
                    cpa16(ab + dO1, sH1 + boff, szB);
                    uint32_t sb = uStage + (uint32_t)(((ch + 1) & 1) * 16384);
                    const float* us = uSrc + (size_t)(ch + 1) * 64 * I_DIM;
                    #pragma unroll
                    for (int q = 0; q < 4; q++)
                        cpa16(sb + stDstBase + q * 16, us + q * 4, 16);
                    CPA_COMMIT();
                    int k0n = (ch + 1) * 64;
                    #pragma unroll
                    for (int it = 0; it < 4; it++) {
                        const float* p = wgB + (size_t)(k0n + (pkb + it * 4) * 4) * I_DIM + pn;
                        bw[it][0] = p[0]; bw[it][1] = p[I_DIM];
                        bw[it][2] = p[2 * I_DIM]; bw[it][3] = p[3 * I_DIM];
                    }
                }

                uint32_t uAhi = uA + (uint32_t)((ch & 1) * 8192);
                uint32_t uBh = uB + (uint32_t)((ch & 1) * 16384);
                #pragma unroll
                for (int ks = 0; ks < 4; ks++) {
                    uint32_t ah[2][4];
                    #pragma unroll
                    for (int mf = 0; mf < 2; mf++) {
                        uint32_t o = SWZB((uint32_t)((aRow + mf * 16) * 128) + (uint32_t)(ks * 32) + aKb);
                        ldm4(ah[mf], uAhi + o);
                    }
                    uint32_t ob1 = SWZB((uint32_t)(bRow * 128) + (uint32_t)(ks * 32) + bKb);
                    uint32_t ob2 = SWZB((uint32_t)((bRow + 16) * 128) + (uint32_t)(ks * 32) + bKb);
                    uint32_t bh[8];
                    ldm4(bh, uBh + ob1);
                    ldm4(bh + 4, uBh + ob2);
                    #pragma unroll
                    for (int mf = 0; mf < 2; mf++) {
                        #pragma unroll
                        for (int nf = 0; nf < 4; nf++) {
                            mma16816(acc[mf][nf], ah[mf], bh[nf * 2], bh[nf * 2 + 1]);
                        }
                    }
                }
                // no trailing sync: A/B/stage all double-buffered
            }

            // epilogue: stage accs to smem (A+B region), a = silu(g)*u, write fp16
            __syncthreads();
            float* stg = (float*)dsm;
            #pragma unroll
            for (int mf = 0; mf < 2; mf++) {
                #pragma unroll
                for (int nf = 0; nf < 4; nf++) {
                    int col = wn * 32 + nf * 8 + lc;
                    #pragma unroll
                    for (int half = 0; half < 2; half++) {
                        int row = wm * 32 + mf * 16 + lr + half * 8;
                        *(float2*)&stg[row * 128 + col] =
                            make_float2(acc[mf][nf][half * 2], acc[mf][nf][half * 2 + 1]);
                    }
                }
            }
            __syncthreads();
            #pragma unroll
            for (int p = 0; p < 8; p++) {
                int idx2 = tid + p * 256;
                int row = idx2 >> 5;
                int cp = idx2 & 31;
                int rid = s_rids[row];
                if (rid >= 0) {
                    float2 g = *(float2*)&stg[row * 128 + cp * 2];
                    float2 u = *(float2*)&stg[row * 128 + 64 + cp * 2];
                    float a0 = (g.x / (1.f + expf(-g.x))) * u.x;
                    float a1 = (g.y / (1.f + expf(-g.y))) * u.y;
                    size_t off = (size_t)rid * I_DIM + nt * 64 + cp * 2;
                    *(uint32_t*)(g_ahi + off) = cvt2h(a0, a1);
                }
            }
            __threadfence();
            __syncthreads();
            if (tid == 0) atomicAdd(&g_rdy[pidx], 1);
        } else {
            // ================= DOWN TILE (1-term A) =================
            int w2 = widx - npair * 8;
            int pidx = w2 >> 3;
            int nt = w2 & 7;
            int pr = g_pairs[pidx];
            int e = pr >> 2, mt = pr & 3;
            int ne = g_cnt[e];
            int m0 = mt * 64;

            if (tid == 0) {
                while (atomicAdd(&g_rdy[pidx], 0) < 8) { }
            }
            __syncthreads();

            if (tid < 64) {
                int i = m0 + tid;
                if (i < ne) {
                    int tk = g_tok[e * T_TOK + i];
                    s_rids[tid] = tk * TOPK + g_slot[e * T_TOK + i];
                    s_wts[tid]  = g_wt[e * T_TOK + i];
                } else { s_rids[tid] = -1; s_wts[tid] = 0.f; }
            }
            __syncthreads();

            int ridA = s_rids[arow0], ridB = s_rids[arow1];
            const char* sH0 = (const char*)g_ahi + ((size_t)(ridA < 0 ? 0 : ridA) * I_DIM) * 2 + aseg * 16;
            const char* sH1 = (const char*)g_ahi + ((size_t)(ridB < 0 ? 0 : ridB) * I_DIM) * 2 + aseg * 16;
            uint32_t szA = (ridA >= 0) ? 16u : 0u;
            uint32_t szB = (ridB >= 0) ? 16u : 0u;

            float acc[2][4][4];
            #pragma unroll
            for (int a = 0; a < 2; a++)
                #pragma unroll
                for (int b = 0; b < 4; b++)
                    #pragma unroll
                    for (int c = 0; c < 4; c++) acc[a][b][c] = 0.f;

            const float* wdB = Wd + (size_t)e * I_DIM * H_DIM + nt * 128;
            const float* uSrc = wdB + 64 + (size_t)srow * H_DIM + sq4;
            float bw[4][4];
            #pragma unroll
            for (int it = 0; it < 4; it++) {
                const float* p = wdB + (size_t)((pkb + it * 4) * 4) * H_DIM + pn;
                bw[it][0] = p[0]; bw[it][1] = p[H_DIM];
                bw[it][2] = p[2 * H_DIM]; bw[it][3] = p[3 * H_DIM];
            }
            cpa16(uA + dO0, sH0, szA);
            cpa16(uA + dO1, sH1, szB);
            #pragma unroll
            for (int q = 0; q < 4; q++)
                cpa16(uStage + stDstBase + q * 16, uSrc + q * 4, 16);
            CPA_COMMIT();

            const int NCH = I_DIM / 64;  // 8
            for (int ch = 0; ch < NCH; ch++) {
                CPA_WAIT0();
                __syncthreads();
                {
                    char* BH = dsm + 32768 + (ch & 1) * 16384;
                    const float* stgW = (const float*)(dsm + 65536 + (ch & 1) * 16384);
                    #pragma unroll
                    for (int it = 0; it < 4; it++) {
                        uint32_t h01 = cvt2h(bw[it][0], bw[it][1]);
                        uint32_t h23 = cvt2h(bw[it][2], bw[it][3]);
                        uint32_t o = SWZB((uint32_t)(pn * 128 + (pkb + it * 4) * 8));
                        *(uint2*)(BH + o) = make_uint2(h01, h23);
                        int kb4 = (pkb + it * 4) * 4;
                        float c0 = stgW[(kb4 + 0) * 64 + pn];
                        float c1 = stgW[(kb4 + 1) * 64 + pn];
                        float c2 = stgW[(kb4 + 2) * 64 + pn];
                        float c3 = stgW[(kb4 + 3) * 64 + pn];
                        uint32_t u01 = cvt2h(c0, c1);
                        uint32_t u23 = cvt2h(c2, c3);
                        uint32_t o2 = SWZB((uint32_t)((64 + pn) * 128 + (pkb + it * 4) * 8));
                        *(uint2*)(BH + o2) = make_uint2(u01, u23);
                    }
                }
                __syncthreads();

                if (ch + 1 < NCH) {
                    uint32_t ab = uA + (uint32_t)(((ch + 1) & 1) * 8192);
                    uint32_t boff = (uint32_t)((ch + 1) * 128);
                    cpa16(ab + dO0, sH0 + boff, szA);
                    cpa16(ab + dO1, sH1 + boff, szB);
                    uint32_t sb = uStage + (uint32_t)(((ch + 1) & 1) * 16384);
                    const float* us = uSrc + (size_t)(ch + 1) * 64 * H_DIM;
                    #pragma unroll
                    for (int q = 0; q < 4; q++)
                        cpa16(sb + stDstBase + q * 16, us + q * 4, 16);
                    CPA_COMMIT();
                    int k0n = (ch + 1) * 64;
                    #pragma unroll
                    for (int it = 0; it < 4; it++) {
                        const float* p = wdB + (size_t)(k0n + (pkb + it * 4) * 4) * H_DIM + pn;
                        bw[it][0] = p[0]; bw[it][1] = p[H_DIM];
                        bw[it][2] = p[2 * H_DIM]; bw[it][3] = p[3 * H_DIM];
                    }
                }

                uint32_t uAhi = uA + (uint32_t)((ch & 1) * 8192);
                uint32_t uBh = uB + (uint32_t)((ch & 1) * 16384);
                #pragma unroll
                for (int ks = 0; ks < 4; ks++) {
                    uint32_t ah[2][4];
                    #pragma unroll
                    for (int mf = 0; mf < 2; mf++) {
                        uint32_t o = SWZB((uint32_t)((aRow + mf * 16) * 128) + (uint32_t)(ks * 32) + aKb);
                        ldm4(ah[mf], uAhi + o);
                    }
                    uint32_t ob1 = SWZB((uint32_t)(bRow * 128) + (uint32_t)(ks * 32) + bKb);
                    uint32_t ob2 = SWZB((uint32_t)((bRow + 16) * 128) + (uint32_t)(ks * 32) + bKb);
                    uint32_t bh[8];
                    ldm4(bh, uBh + ob1);
                    ldm4(bh + 4, uBh + ob2);
                    #pragma unroll
                    for (int mf = 0; mf < 2; mf++) {
                        #pragma unroll
                        for (int nf = 0; nf < 4; nf++) {
                            mma16816(acc[mf][nf], ah[mf], bh[nf * 2], bh[nf * 2 + 1]);
                        }
                    }
                }
                // no trailing sync
            }

            #pragma unroll
            for (int mf = 0; mf < 2; mf++) {
                #pragma unroll
                for (int nf = 0; nf < 4; nf++) {
                    int col = nt * 128 + wn * 32 + nf * 8 + lc;
                    #pragma unroll
                    for (int half = 0; half < 2; half++) {
                        int row = wm * 32 + mf * 16 + lr + half * 8;
                        if (m0 + row < ne) {
                            int rid = s_rids[row];
                            float wt = s_wts[row];
                            float2 o;
                            o.x = wt * acc[mf][nf][half * 2 + 0];
                            o.y = wt * acc[mf][nf][half * 2 + 1];
                            *(float2*)(g_ybuf + (size_t)rid * H_DIM + col) = o;
                        }
                    }
                }
            }
        }
    }
}

// ---------------- kernel: deterministic combine ----------------
__global__ __launch_bounds__(256) void combine_kernel(float* __restrict__ out)
{
    int idx = blockIdx.x * 256 + threadIdx.x;
    int t = idx >> 10;
    int h = idx & 1023;
    float s = 0.f;
    #pragma unroll
    for (int k = 0; k < TOPK; k++)
        s += g_ybuf[((size_t)t * TOPK + k) * H_DIM + h];
    out[idx] = s;
}

// ---------------- launch ----------------
#define GEMM_SMEM (32768 + 32768 + 32768)   // 96KB
#define N_PERSIST 296

extern "C" void kernel_launch(void* const* d_in, const int* in_sizes, int n_in,
                              void* d_out, int out_size)
{
    const float* x      = (const float*)d_in[0];
    const float* gate_w = (const float*)d_in[1];
    const float* bias   = (const float*)d_in[2];
    const float* Wg     = (const float*)d_in[3];
    const float* Wu     = (const float*)d_in[4];
    const float* Wd     = (const float*)d_in[5];
    float* out = (float*)d_out;

    cudaFuncSetAttribute(moe_gemm_kernel, cudaFuncAttributeMaxDynamicSharedMemorySize, GEMM_SMEM);

    routing_kernel<<<T_TOK, 128>>>(x, gate_w, bias);
    build_lists_kernel<<<1, 1024>>>();
    moe_gemm_kernel<<<N_PERSIST, 256, GEMM_SMEM>>>(Wg, Wu, Wd);
    combine_kernel<<<(T_TOK * H_DIM) / 256, 256>>>(out);
}

// round 17
// speedup vs baseline: 1.3312x; 1.0336x over previous
#include <cuda_runtime.h>
#include <cuda_bf16.h>
#include <cuda_fp16.h>
#include <math.h>
#include <stdint.h>

#define T_TOK 256
#define H_DIM 1024
#define I_DIM 512
#define E_EXP 32
#define TOPK  8
#define NGRP  8
#define GSZ   4
#define TKG   4

#define SWZB(o) ((o) ^ (((o) >> 3) & 0x70))

// ---------------- helpers ----------------
__device__ __forceinline__ uint32_t smem_u32(const void* p) {
    uint32_t a;
    asm("{ .reg .u64 t; cvta.to.shared.u64 t, %1; cvt.u32.u64 %0, t; }" : "=r"(a) : "l"(p));
    return a;
}

// pack 2 fp32 -> fp16x2 (e0 low half, e1 high half), rn
__device__ __forceinline__ uint32_t cvt2h(float e0, float e1) {
    uint32_t h;
    asm("cvt.rn.f16x2.f32 %0, %1, %2;" : "=r"(h) : "f"(e1), "f"(e0));
    return h;
}

__device__ __forceinline__ void ldm4(uint32_t r[4], uint32_t addr) {
    asm volatile("ldmatrix.sync.aligned.m8n8.x4.shared.b16 {%0,%1,%2,%3}, [%4];"
        : "=r"(r[0]), "=r"(r[1]), "=r"(r[2]), "=r"(r[3]) : "r"(addr));
}

__device__ __forceinline__ void mma16816(float d[4], const uint32_t a[4],
                                         uint32_t b0, uint32_t b1) {
    asm volatile("mma.sync.aligned.m16n8k16.row.col.f32.f16.f16.f32 "
        "{%0,%1,%2,%3}, {%4,%5,%6,%7}, {%8,%9}, {%0,%1,%2,%3};"
        : "+f"(d[0]), "+f"(d[1]), "+f"(d[2]), "+f"(d[3])
        : "r"(a[0]), "r"(a[1]), "r"(a[2]), "r"(a[3]), "r"(b0), "r"(b1));
}

__device__ __forceinline__ void cpa16(uint32_t dst, const void* src, uint32_t sz) {
    asm volatile("cp.async.cg.shared.global [%0], [%1], 16, %2;"
        :: "r"(dst), "l"(src), "r"(sz) : "memory");
}
#define CPA_COMMIT() asm volatile("cp.async.commit_group;" ::: "memory")
#define CPA_WAIT0()  asm volatile("cp.async.wait_group 0;" ::: "memory")

// ---------------- device scratch ----------------
__device__ int   g_topk_idx[T_TOK * TOPK];
__device__ float g_topk_w[T_TOK * TOPK];
__device__ int   g_cnt[E_EXP];
__device__ int   g_tok[E_EXP * T_TOK];
__device__ int   g_slot[E_EXP * T_TOK];
__device__ float g_wt[E_EXP * T_TOK];
__device__ uint16_t g_xhi[T_TOK * H_DIM];          // fp16(x)
__device__ uint16_t g_ahi[T_TOK * TOPK * I_DIM];   // fp16(a)
__device__ float g_ybuf[T_TOK * TOPK * H_DIM];

// work queue
__device__ int g_pairs[E_EXP * 4];
__device__ int g_npair;
__device__ int g_ctr;
__device__ int g_rdy[E_EXP * 4];

// ---------------- kernel 1: routing (coalesced GEMV + fused x->fp16) ----------------
__global__ __launch_bounds__(128) void routing_kernel(
    const float* __restrict__ x, const float* __restrict__ gate_w,
    const float* __restrict__ bias)
{
    int t = blockIdx.x;
    __shared__ float xs[H_DIM];
    __shared__ float part[4][E_EXP];
    __shared__ float sc[E_EXP];
    __shared__ float sfc[E_EXP];
    int tid = threadIdx.x;
    for (int i = tid; i < H_DIM / 4; i += 128) {
        float4 v = *(const float4*)(x + (size_t)t * H_DIM + i * 4);
        *(float4*)&xs[i * 4] = v;
        uint32_t h0 = cvt2h(v.x, v.y);
        uint32_t h1 = cvt2h(v.z, v.w);
        ((uint2*)(g_xhi + (size_t)t * H_DIM))[i] = make_uint2(h0, h1);
    }
    __syncthreads();
    int warp = tid >> 5, lane = tid & 31;
    {
        float s = 0.f;
        const float* gw = gate_w + lane;
        int h0 = warp * (H_DIM / 4);
        #pragma unroll 4
        for (int h = h0; h < h0 + H_DIM / 4; h++)
            s += xs[h] * gw[(size_t)h * E_EXP];
        part[warp][lane] = s;
    }
    __syncthreads();
    if (tid < E_EXP) {
        float s = part[0][tid] + part[1][tid] + part[2][tid] + part[3][tid];
        float sig = 1.f / (1.f + expf(-s));
        sc[tid] = sig;
        sfc[tid] = sig + bias[tid];
    }
    __syncthreads();
    if (tid == 0) {
        float gs[NGRP];
        #pragma unroll
        for (int g = 0; g < NGRP; g++) {
            float m1 = -1e30f, m2 = -1e30f;
            #pragma unroll
            for (int j = 0; j < GSZ; j++) {
                float v = sfc[g * GSZ + j];
                if (v > m1) { m2 = m1; m1 = v; }
                else if (v > m2) { m2 = v; }
            }
            gs[g] = m1 + m2;
        }
        bool gsel[NGRP];
        #pragma unroll
        for (int g = 0; g < NGRP; g++) gsel[g] = false;
        for (int r = 0; r < TKG; r++) {
            int b = -1;
            for (int g = 0; g < NGRP; g++)
                if (!gsel[g] && (b < 0 || gs[g] > gs[b])) b = g;
            gsel[b] = true;
        }
        float masked[E_EXP];
        bool used[E_EXP];
        #pragma unroll
        for (int e = 0; e < E_EXP; e++) {
            masked[e] = gsel[e >> 2] ? sfc[e] : 0.0f;
            used[e] = false;
        }
        int idx[TOPK];
        float wsum = 0.f;
        for (int r = 0; r < TOPK; r++) {
            int b = -1;
            for (int e = 0; e < E_EXP; e++)
                if (!used[e] && (b < 0 || masked[e] > masked[b])) b = e;
            used[b] = true;
            idx[r] = b;
            wsum += sc[b];
        }
        float scale = 2.5f / (wsum + 1e-20f);
        for (int r = 0; r < TOPK; r++) {
            g_topk_idx[t * TOPK + r] = idx[r];
            g_topk_w[t * TOPK + r]   = sc[idx[r]] * scale;
        }
    }
}

// ---------------- kernel 2: compaction + work-queue setup ----------------
__global__ __launch_bounds__(1024) void build_lists_kernel()
{
    int e = threadIdx.x >> 5;
    int lane = threadIdx.x & 31;
    int cnt = 0;
    for (int t0 = 0; t0 < T_TOK; t0 += 32) {
        int t = t0 + lane;
        int found = -1;
        #pragma unroll
        for (int k = 0; k < TOPK; k++)
            if (g_topk_idx[t * TOPK + k] == e) found = k;
        unsigned m = __ballot_sync(0xffffffffu, found >= 0);
        if (found >= 0) {
            int pos = cnt + __popc(m & ((1u << lane) - 1));
            g_tok [e * T_TOK + pos] = t;
            g_slot[e * T_TOK + pos] = found;
            g_wt  [e * T_TOK + pos] = g_topk_w[t * TOPK + found];
        }
        cnt += __popc(m);
    }
    if (lane == 0) g_cnt[e] = cnt;
    if (threadIdx.x < E_EXP * 4) g_rdy[threadIdx.x] = 0;
    __syncthreads();
    if (threadIdx.x == 0) {
        int n = 0;
        for (int ee = 0; ee < E_EXP; ee++) {
            int c = g_cnt[ee];
            for (int mt = 0; mt * 64 < c; mt++) g_pairs[n++] = (ee << 2) | mt;
        }
        g_npair = n;
        g_ctr = 0;
    }
}

// ---------------- fused persistent GEMM kernel (fp16 1-term, hoisted prefetch) ----------------
// smem (96KB): A [0,32K): buf0 8K, buf1 8K; B fp16 double [32K,64K);
// W fp32 stage double [64K,96K).  Per chunk: sync1 -> issue cp.async(ch+1) ->
// convert(ch) -> sync2 -> LDG bw(ch+1) -> MMA(ch).

__global__ __launch_bounds__(256, 2) void moe_gemm_kernel(
    const float* __restrict__ Wg,
    const float* __restrict__ Wu,
    const float* __restrict__ Wd)
{
    extern __shared__ __align__(128) char dsm[];
    __shared__ int   s_widx;
    __shared__ int   s_toks[64];
    __shared__ int   s_rids[64];
    __shared__ float s_wts[64];

    int tid = threadIdx.x;
    int lane = tid & 31;
    int w = tid >> 5;
    int wm = w & 1;
    int wn = w >> 1;

    uint32_t uA = smem_u32(dsm);
    uint32_t uB = uA + 32768;
    uint32_t uStage = uA + 65536;

    int arow0 = tid >> 3, aseg = tid & 7;
    int arow1 = arow0 + 32;
    uint32_t dO0 = SWZB((uint32_t)(arow0 * 128 + aseg * 16));
    uint32_t dO1 = SWZB((uint32_t)(arow1 * 128 + aseg * 16));

    int srow = tid >> 2;
    int sq4  = (tid & 3) * 16;
    uint32_t stDstBase = (uint32_t)(srow * 256 + (tid & 3) * 64);

    int aRow = wm * 32 + (lane & 15);
    uint32_t aKb = (uint32_t)((lane >> 4) * 16);
    int bRow = wn * 32 + (lane & 7) + ((lane >> 4) << 3);
    uint32_t bKb = (uint32_t)(((lane >> 3) & 1) * 16);

    int pkb = tid >> 6, pn = tid & 63;
    int lr = lane >> 2, lc = (lane & 3) * 2;

    for (;;) {
        __syncthreads();
        if (tid == 0) s_widx = atomicAdd(&g_ctr, 1);
        __syncthreads();
        int widx = s_widx;
        int npair = g_npair;
        if (widx >= npair * 16) return;

        if (widx < npair * 8) {
            // ================= GATEUP TILE =================
            int pidx = widx >> 3;
            int nt = widx & 7;
            int pr = g_pairs[pidx];
            int e = pr >> 2, mt = pr & 3;
            int ne = g_cnt[e];
            int m0 = mt * 64;

            if (tid < 64) {
                int i = m0 + tid;
                if (i < ne) {
                    int tk = g_tok[e * T_TOK + i];
                    s_toks[tid] = tk;
                    s_rids[tid] = tk * TOPK + g_slot[e * T_TOK + i];
                } else { s_toks[tid] = -1; s_rids[tid] = -1; }
            }
            __syncthreads();

            int tokA = s_toks[arow0], tokB = s_toks[arow1];
            const char* sH0 = (const char*)g_xhi + ((size_t)(tokA < 0 ? 0 : tokA) * H_DIM) * 2 + aseg * 16;
            const char* sH1 = (const char*)g_xhi + ((size_t)(tokB < 0 ? 0 : tokB) * H_DIM) * 2 + aseg * 16;
            uint32_t szA = (tokA >= 0) ? 16u : 0u;
            uint32_t szB = (tokB >= 0) ? 16u : 0u;

            float acc[2][4][4];
            #pragma unroll
            for (int a = 0; a < 2; a++)
                #pragma unroll
                for (int b = 0; b < 4; b++)
                    #pragma unroll
                    for (int c = 0; c < 4; c++) acc[a][b][c] = 0.f;

            const float* wgB = Wg + (size_t)e * H_DIM * I_DIM + nt * 64;
            const float* wuB = Wu + (size_t)e * H_DIM * I_DIM + nt * 64;
            const float* uSrc = wuB + (size_t)srow * I_DIM + sq4;

            float bw[4][4];
            #pragma unroll
            for (int it = 0; it < 4; it++) {
                const float* p = wgB + (size_t)((pkb + it * 4) * 4) * I_DIM + pn;
                bw[it][0] = p[0]; bw[it][1] = p[I_DIM];
                bw[it][2] = p[2 * I_DIM]; bw[it][3] = p[3 * I_DIM];
            }
            cpa16(uA + dO0, sH0, szA);
            cpa16(uA + dO1, sH1, szB);
            #pragma unroll
            for (int q = 0; q < 4; q++)
                cpa16(uStage + stDstBase + q * 16, uSrc + q * 4, 16);
            CPA_COMMIT();

            const int NCH = H_DIM / 64;  // 16
            for (int ch = 0; ch < NCH; ch++) {
                CPA_WAIT0();
                __syncthreads();   // sync1: cp.async visibility, MMA(ch-1) done
                // hoisted: issue cp.async for ch+1 (buffers free per race analysis)
                if (ch + 1 < NCH) {
                    uint32_t ab = uA + (uint32_t)(((ch + 1) & 1) * 8192);
                    uint32_t boff = (uint32_t)((ch + 1) * 128);
                    cpa16(ab + dO0, sH0 + boff, szA);
                    cpa16(ab + dO1, sH1 + boff, szB);
                    uint32_t sb = uStage + (uint32_t)(((ch + 1) & 1) * 16384);
                    const float* us = uSrc + (size_t)(ch + 1) * 64 * I_DIM;
                    #pragma unroll
                    for (int q = 0; q < 4; q++)
                        cpa16(sb + stDstBase + q * 16, us + q * 4, 16);
                    CPA_COMMIT();
                }
                // convert(ch): B[ch&1] <- g (regs) + u (stage LDS)
                {
                    char* BH = dsm + 32768 + (ch & 1) * 16384;
                    const float* stgW = (const float*)(dsm + 65536 + (ch & 1) * 16384);
                    #pragma unroll
                    for (int it = 0; it < 4; it++) {
                        uint32_t h01 = cvt2h(bw[it][0], bw[it][1]);
                        uint32_t h23 = cvt2h(bw[it][2], bw[it][3]);
                        uint32_t o = SWZB((uint32_t)(pn * 128 + (pkb + it * 4) * 8));
                        *(uint2*)(BH + o) = make_uint2(h01, h23);
                        int kb4 = (pkb + it * 4) * 4;
                        float c0 = stgW[(kb4 + 0) * 64 + pn];
                        float c1 = stgW[(kb4 + 1) * 64 + pn];
                        float c2 = stgW[(kb4 + 2) * 64 + pn];
                        float c3 = stgW[(kb4 + 3) * 64 + pn];
                        uint32_t u01 = cvt2h(c0, c1);
                        uint32_t u23 = cvt2h(c2, c3);
                        uint32_t o2 = SWZB((uint32_t)((64 + pn) * 128 + (pkb + it * 4) * 8));
                        *(uint2*)(BH + o2) = make_uint2(u01, u23);
                    }
                }
                __syncthreads();   // sync2: B[ch&1] ready

                if (ch + 1 < NCH) {
                    int k0n = (ch + 1) * 64;
                    #pragma unroll
                    for (int it = 0; it < 4; it++) {
                        const float* p = wgB + (size_t)(k0n + (pkb + it * 4) * 4) * I_DIM + pn;
                        bw[it][0] = p[0]; bw[it][1] = p[I_DIM];
                        bw[it][2] = p[2 * I_DIM]; bw[it][3] = p[3 * I_DIM];
                    }
                }

                uint32_t uAhi = uA + (uint32_t)((ch & 1) * 8192);
                uint32_t uBh = uB + (uint32_t)((ch & 1) * 16384);
                #pragma unroll
                for (int ks = 0; ks < 4; ks++) {
                    uint32_t ah[2][4];
                    #pragma unroll
                    for (int mf = 0; mf < 2; mf++) {
                        uint32_t o = SWZB((uint32_t)((aRow + mf * 16) * 128) + (uint32_t)(ks * 32) + aKb);
                        ldm4(ah[mf], uAhi + o);
                    }
                    uint32_t ob1 = SWZB((uint32_t)(bRow * 128) + (uint32_t)(ks * 32) + bKb);
                    uint32_t ob2 = SWZB((uint32_t)((bRow + 16) * 128) + (uint32_t)(ks * 32) + bKb);
                    uint32_t bh[8];
                    ldm4(bh, uBh + ob1);
                    ldm4(bh + 4, uBh + ob2);
                    #pragma unroll
                    for (int mf = 0; mf < 2; mf++) {
                        #pragma unroll
                        for (int nf = 0; nf < 4; nf++) {
                            mma16816(acc[mf][nf], ah[mf], bh[nf * 2], bh[nf * 2 + 1]);
                        }
                    }
                }
            }

            // epilogue: stage accs to smem, a = silu(g)*u, write fp16
            __syncthreads();
            float* stg = (float*)dsm;
            #pragma unroll
            for (int mf = 0; mf < 2; mf++) {
                #pragma unroll
                for (int nf = 0; nf < 4; nf++) {
                    int col = wn * 32 + nf * 8 + lc;
                    #pragma unroll
                    for (int half = 0; half < 2; half++) {
                        int row = wm * 32 + mf * 16 + lr + half * 8;
                        *(float2*)&stg[row * 128 + col] =
                            make_float2(acc[mf][nf][half * 2], acc[mf][nf][half * 2 + 1]);
                    }
                }
            }
            __syncthreads();
            #pragma unroll
            for (int p = 0; p < 8; p++) {
                int idx2 = tid + p * 256;
                int row = idx2 >> 5;
                int cp = idx2 & 31;
                int rid = s_rids[row];
                if (rid >= 0) {
                    float2 g = *(float2*)&stg[row * 128 + cp * 2];
                    float2 u = *(float2*)&stg[row * 128 + 64 + cp * 2];
                    float a0 = (g.x / (1.f + expf(-g.x))) * u.x;
                    float a1 = (g.y / (1.f + expf(-g.y))) * u.y;
                    size_t off = (size_t)rid * I_DIM + nt * 64 + cp * 2;
                    *(uint32_t*)(g_ahi + off) = cvt2h(a0, a1);
                }
            }
            __threadfence();
            __syncthreads();
            if (tid == 0) atomicAdd(&g_rdy[pidx], 1);
        } else {
            // ================= DOWN TILE =================
            int w2 = widx - npair * 8;
            int pidx = w2 >> 3;
            int nt = w2 & 7;
            int pr = g_pairs[pidx];
            int e = pr >> 2, mt = pr & 3;
            int ne = g_cnt[e];
            int m0 = mt * 64;

            if (tid == 0) {
                while (atomicAdd(&g_rdy[pidx], 0) < 8) { }
            }
            __syncthreads();

            if (tid < 64) {
                int i = m0 + tid;
                if (i < ne) {
                    int tk = g_tok[e * T_TOK + i];
                    s_rids[tid] = tk * TOPK + g_slot[e * T_TOK + i];
                    s_wts[tid]  = g_wt[e * T_TOK + i];
                } else { s_rids[tid] = -1; s_wts[tid] = 0.f; }
            }
            __syncthreads();

            int ridA = s_rids[arow0], ridB = s_rids[arow1];
            const char* sH0 = (const char*)g_ahi + ((size_t)(ridA < 0 ? 0 : ridA) * I_DIM) * 2 + aseg * 16;
            const char* sH1 = (const char*)g_ahi + ((size_t)(ridB < 0 ? 0 : ridB) * I_DIM) * 2 + aseg * 16;
            uint32_t szA = (ridA >= 0) ? 16u : 0u;
            uint32_t szB = (ridB >= 0) ? 16u : 0u;

            float acc[2][4][4];
            #pragma unroll
            for (int a = 0; a < 2; a++)
                #pragma unroll
                for (int b = 0; b < 4; b++)
                    #pragma unroll
                    for (int c = 0; c < 4; c++) acc[a][b][c] = 0.f;

            const float* wdB = Wd + (size_t)e * I_DIM * H_DIM + nt * 128;
            const float* uSrc = wdB + 64 + (size_t)srow * H_DIM + sq4;
            float bw[4][4];
            #pragma unroll
            for (int it = 0; it < 4; it++) {
                const float* p = wdB + (size_t)((pkb + it * 4) * 4) * H_DIM + pn;
                bw[it][0] = p[0]; bw[it][1] = p[H_DIM];
                bw[it][2] = p[2 * H_DIM]; bw[it][3] = p[3 * H_DIM];
            }
            cpa16(uA + dO0, sH0, szA);
            cpa16(uA + dO1, sH1, szB);
            #pragma unroll
            for (int q = 0; q < 4; q++)
                cpa16(uStage + stDstBase + q * 16, uSrc + q * 4, 16);
            CPA_COMMIT();

            const int NCH = I_DIM / 64;  // 8
            for (int ch = 0; ch < NCH; ch++) {
                CPA_WAIT0();
                __syncthreads();
                if (ch + 1 < NCH) {
                    uint32_t ab = uA + (uint32_t)(((ch + 1) & 1) * 8192);
                    uint32_t boff = (uint32_t)((ch + 1) * 128);
                    cpa16(ab + dO0, sH0 + boff, szA);
                    cpa16(ab + dO1, sH1 + boff, szB);
                    uint32_t sb = uStage + (uint32_t)(((ch + 1) & 1) * 16384);
                    const float* us = uSrc + (size_t)(ch + 1) * 64 * H_DIM;
                    #pragma unroll
                    for (int q = 0; q < 4; q++)
                        cpa16(sb + stDstBase + q * 16, us + q * 4, 16);
                    CPA_COMMIT();
                }
                {
                    char* BH = dsm + 32768 + (ch & 1) * 16384;
                    const float* stgW = (const float*)(dsm + 65536 + (ch & 1) * 16384);
                    #pragma unroll
                    for (int it = 0; it < 4; it++) {
                        uint32_t h01 = cvt2h(bw[it][0], bw[it][1]);
                        uint32_t h23 = cvt2h(bw[it][2], bw[it][3]);
                        uint32_t o = SWZB((uint32_t)(pn * 128 + (pkb + it * 4) * 8));
                        *(uint2*)(BH + o) = make_uint2(h01, h23);
                        int kb4 = (pkb + it * 4) * 4;
                        float c0 = stgW[(kb4 + 0) * 64 + pn];
                        float c1 = stgW[(kb4 + 1) * 64 + pn];
                        float c2 = stgW[(kb4 + 2) * 64 + pn];
                        float c3 = stgW[(kb4 + 3) * 64 + pn];
                        uint32_t u01 = cvt2h(c0, c1);
                        uint32_t u23 = cvt2h(c2, c3);
                        uint32_t o2 = SWZB((uint32_t)((64 + pn) * 128 + (pkb + it * 4) * 8));
                        *(uint2*)(BH + o2) = make_uint2(u01, u23);
                    }
                }
                __syncthreads();

                if (ch + 1 < NCH) {
                    int k0n = (ch + 1) * 64;
                    #pragma unroll
                    for (int it = 0; it < 4; it++) {
                        const float* p = wdB + (size_t)(k0n + (pkb + it * 4) * 4) * H_DIM + pn;
                        bw[it][0] = p[0]; bw[it][1] = p[H_DIM];
                        bw[it][2] = p[2 * H_DIM]; bw[it][3] = p[3 * H_DIM];
                    }
                }

                uint32_t uAhi = uA + (uint32_t)((ch & 1) * 8192);
                uint32_t uBh = uB + (uint32_t)((ch & 1) * 16384);
                #pragma unroll
                for (int ks = 0; ks < 4; ks++) {
                    uint32_t ah[2][4];
                    #pragma unroll
                    for (int mf = 0; mf < 2; mf++) {
                        uint32_t o = SWZB((uint32_t)((aRow + mf * 16) * 128) + (uint32_t)(ks * 32) + aKb);
                        ldm4(ah[mf], uAhi + o);
                    }
                    uint32_t ob1 = SWZB((uint32_t)(bRow * 128) + (uint32_t)(ks * 32) + bKb);
                    uint32_t ob2 = SWZB((uint32_t)((bRow + 16) * 128) + (uint32_t)(ks * 32) + bKb);
                    uint32_t bh[8];
                    ldm4(bh, uBh + ob1);
                    ldm4(bh + 4, uBh + ob2);
                    #pragma unroll
                    for (int mf = 0; mf < 2; mf++) {
                        #pragma unroll
                        for (int nf = 0; nf < 4; nf++) {
                            mma16816(acc[mf][nf], ah[mf], bh[nf * 2], bh[nf * 2 + 1]);
                        }
                    }
                }
            }

            #pragma unroll
            for (int mf = 0; mf < 2; mf++) {
                #pragma unroll
                for (int nf = 0; nf < 4; nf++) {
                    int col = nt * 128 + wn * 32 + nf * 8 + lc;
                    #pragma unroll
                    for (int half = 0; half < 2; half++) {
                        int row = wm * 32 + mf * 16 + lr + half * 8;
                        if (m0 + row < ne) {
                            int rid = s_rids[row];
                            float wt = s_wts[row];
                            float2 o;
                            o.x = wt * acc[mf][nf][half * 2 + 0];
                            o.y = wt * acc[mf][nf][half * 2 + 1];
                            *(float2*)(g_ybuf + (size_t)rid * H_DIM + col) = o;
                        }
                    }
                }
            }
        }
    }
}

// ---------------- kernel: deterministic combine ----------------
__global__ __launch_bounds__(256) void combine_kernel(float* __restrict__ out)
{
    int idx = blockIdx.x * 256 + threadIdx.x;
    int t = idx >> 10;
    int h = idx & 1023;
    float s = 0.f;
    #pragma unroll
    for (int k = 0; k < TOPK; k++)
        s += g_ybuf[((size_t)t * TOPK + k) * H_DIM + h];
    out[idx] = s;
}

// ---------------- launch ----------------
#define GEMM_SMEM (32768 + 32768 + 32768)   // 96KB
#define N_PERSIST 296

extern "C" void kernel_launch(void* const* d_in, const int* in_sizes, int n_in,
                              void* d_out, int out_size)
{
    const float* x      = (const float*)d_in[0];
    const float* gate_w = (const float*)d_in[1];
    const float* bias   = (const float*)d_in[2];
    const float* Wg     = (const float*)d_in[3];
    const float* Wu     = (const float*)d_in[4];
    const float* Wd     = (const float*)d_in[5];
    float* out = (float*)d_out;

    cudaFuncSetAttribute(moe_gemm_kernel, cudaFuncAttributeMaxDynamicSharedMemorySize, GEMM_SMEM);

    routing_kernel<<<T_TOK, 128>>>(x, gate_w, bias);
    build_lists_kernel<<<1, 1024>>>();
    moe_gemm_kernel<<<N_PERSIST, 256, GEMM_SMEM>>>(Wg, Wu, Wd);
    combine_kernel<<<(T_TOK * H_DIM) / 256, 256>>>(out);
}